// round 10
// baseline (speedup 1.0000x reference)
#include <cuda_runtime.h>
#include <cstdint>

#define NN 100000
#define EE 600000
#define ELN 200000

// ---------------- device scratch ----------------
__device__ float g_h[(size_t)NN * 64];    // layer1 node projections
__device__ float g_z1[(size_t)NN * 64];   // layer1 output
__device__ float g_u2[(size_t)NN * 64];   // z1 + nt2[type]
__device__ float g_v2[(size_t)NN * 408];  // layer2 aggregates [yh 256 | ea 64 | hist 88]
__device__ float g_M2[408 * 64];          // stacked layer2 epilogue matrix (pre-scaled 0.25)
__device__ float g_sc[(size_t)EE * 4];    // CSR-ordered scores
__device__ float g_ss[NN * 4];
__device__ float g_sd[NN * 4];
__device__ int   g_cnt[NN];
__device__ int   g_rowptr[NN + 1];
__device__ int   g_cur[NN];
__device__ int   g_pos[EE];               // edge -> CSR slot
__device__ int2  g_meta[EE];              // CSR slot -> (src, etype)
__device__ int   g_eorig[EE];             // CSR slot -> original edge id
__device__ float g_wae1[64], g_tae1[88];
__device__ float g_wae2[64], g_tae2[88];
__device__ float g_was2[256], g_wad2[256]; // [h*64+k] = sum_c Wx2[k][h*64+c]*a[h*64+c]

// ---------------- CSR build ----------------
__global__ void k_count(const int* __restrict__ ei) {
    int e = blockIdx.x * blockDim.x + threadIdx.x;
    if (e < EE) atomicAdd(&g_cnt[ei[EE + e]], 1);
}

__global__ void k_scanfuse(const float* __restrict__ We1, const float* __restrict__ ae1,
                           const float* __restrict__ et1,
                           const float* __restrict__ We2, const float* __restrict__ ae2,
                           const float* __restrict__ et2,
                           const float* __restrict__ Wx2, const float* __restrict__ as2,
                           const float* __restrict__ ad2) {
    __shared__ int sp[1024];
    int tid = threadIdx.x;
    if (tid < 64) {
        int k = tid >> 2, h = tid & 3;
        float s = 0.f;
        for (int d = 0; d < 16; d++) s += We1[k * 64 + h * 16 + d] * ae1[h * 16 + d];
        g_wae1[k * 4 + h] = s;
        float s2 = 0.f;
        for (int d = 0; d < 64; d++) s2 += We2[k * 256 + h * 64 + d] * ae2[h * 64 + d];
        g_wae2[k * 4 + h] = s2;
    }
    if (tid < 88) {
        int t = tid >> 2, h = tid & 3;
        float s = 0.f;
        for (int d = 0; d < 16; d++) s += et1[t * 64 + h * 16 + d] * ae1[h * 16 + d];
        g_tae1[t * 4 + h] = s;
        float s2 = 0.f;
        for (int d = 0; d < 64; d++) s2 += et2[t * 256 + h * 64 + d] * ae2[h * 64 + d];
        g_tae2[t * 4 + h] = s2;
    }
    if (tid >= 128 && tid < 384) {
        int idx = tid - 128;      // h*64 + k
        int h = idx >> 6, k = idx & 63;
        float s = 0.f, q = 0.f;
        for (int c = 0; c < 64; c++) {
            float w = Wx2[k * 256 + h * 64 + c];
            s += w * as2[h * 64 + c];
            q += w * ad2[h * 64 + c];
        }
        g_was2[idx] = s;
        g_wad2[idx] = q;
    }
    const int chunk = (NN + 1023) >> 10;
    int st = tid * chunk;
    int en = st + chunk; if (en > NN) en = NN;
    int s = 0;
    for (int i = st; i < en; i++) s += g_cnt[i];
    sp[tid] = s;
    __syncthreads();
    for (int o = 1; o < 1024; o <<= 1) {
        int v = (tid >= o) ? sp[tid - o] : 0;
        __syncthreads();
        sp[tid] += v;
        __syncthreads();
    }
    int b = sp[tid] - s;
    for (int i = st; i < en; i++) {
        g_rowptr[i] = b; g_cur[i] = b; b += g_cnt[i];
        g_cnt[i] = 0;   // re-zero for next replay
    }
    if (tid == 1023) g_rowptr[NN] = sp[1023];
}

__global__ void k_fill(const int* __restrict__ ei, const int* __restrict__ etype) {
    int e = blockIdx.x * blockDim.x + threadIdx.x;
    if (e < EE) {
        int d = ei[EE + e];
        int p = atomicAdd(&g_cur[d], 1);
        g_pos[e] = p;
        g_meta[p] = make_int2(ei[e], etype[e]);
        g_eorig[p] = e;
    }
}

// ---------------- layer1 node projection: persistent, Wx in registers ----------------
__global__ void __launch_bounds__(256) k_proj1(const float* __restrict__ x, const int* __restrict__ ntype,
                                               const float* __restrict__ nt, const float* __restrict__ Wx,
                                               const float* __restrict__ a_s, const float* __restrict__ a_d) {
    __shared__ float sNt[8 * 16];
    int tid = threadIdx.x, L = tid & 31, w = tid >> 5;
    for (int i = tid; i < 128; i += 256) sNt[i] = nt[i];

    float W0[16], W1r[16];
#pragma unroll
    for (int k = 0; k < 16; k++) {
        W0[k]  = __ldg(&Wx[k * 64 + L]);
        W1r[k] = __ldg(&Wx[k * 64 + 32 + L]);
    }
    float as0 = __ldg(&a_s[L]), as1 = __ldg(&a_s[32 + L]);
    float ad0 = __ldg(&a_d[L]), ad1 = __ldg(&a_d[32 + L]);
    __syncthreads();

    int nwarps = gridDim.x * 8;
    for (int n = blockIdx.x * 8 + w; n < NN; n += nwarps) {
        int t = __ldg(&ntype[n]);
        float xv = 0.f;
        if (L < 16) xv = __ldg(&x[(size_t)n * 16 + L]) + sNt[t * 16 + L];
        float acc0 = 0.f, acc1 = 0.f;
#pragma unroll
        for (int k = 0; k < 16; k++) {
            float xk = __shfl_sync(0xffffffffu, xv, k);
            acc0 = fmaf(xk, W0[k], acc0);
            acc1 = fmaf(xk, W1r[k], acc1);
        }
        g_h[(size_t)n * 64 + L] = acc0;
        g_h[(size_t)n * 64 + 32 + L] = acc1;

        float pa = acc0 * as0, pb = acc1 * as1;
        float qa = acc0 * ad0, qb = acc1 * ad1;
#pragma unroll
        for (int o = 8; o >= 1; o >>= 1) {
            pa += __shfl_xor_sync(0xffffffffu, pa, o);
            pb += __shfl_xor_sync(0xffffffffu, pb, o);
            qa += __shfl_xor_sync(0xffffffffu, qa, o);
            qb += __shfl_xor_sync(0xffffffffu, qb, o);
        }
        if (L == 0)  { g_ss[n * 4 + 0] = pa; g_ss[n * 4 + 2] = pb; g_sd[n * 4 + 0] = qa; g_sd[n * 4 + 2] = qb; }
        if (L == 16) { g_ss[n * 4 + 1] = pa; g_ss[n * 4 + 3] = pb; g_sd[n * 4 + 1] = qa; g_sd[n * 4 + 3] = qb; }
    }
}

// ---------------- edge scores (raw, post-leaky), scattered to CSR slots ----------------
template <int LAYER>
__global__ void k_score(const int* __restrict__ ei, const float* __restrict__ eattr,
                        const int* __restrict__ etype) {
    __shared__ float sW[64];
    __shared__ float sT[88];
    const float* wae = (LAYER == 1) ? g_wae1 : g_wae2;
    const float* tae = (LAYER == 1) ? g_tae1 : g_tae2;
    if (threadIdx.x < 64) sW[threadIdx.x] = wae[threadIdx.x];
    if (threadIdx.x < 88) sT[threadIdx.x] = tae[threadIdx.x];
    __syncthreads();

    int e = blockIdx.x * blockDim.x + threadIdx.x;
    if (e >= EE) return;
    int s = ei[e], d = ei[EE + e], t = etype[e];
    float sc[4];
#pragma unroll
    for (int h = 0; h < 4; h++)
        sc[h] = g_ss[s * 4 + h] + g_sd[d * 4 + h] + sT[t * 4 + h];

    const float4* ea = (const float4*)(eattr + (size_t)e * 16);
#pragma unroll
    for (int q = 0; q < 4; q++) {
        float4 a = __ldg(ea + q);
#pragma unroll
        for (int h = 0; h < 4; h++) {
            sc[h] = fmaf(a.x, sW[(4 * q + 0) * 4 + h],
                    fmaf(a.y, sW[(4 * q + 1) * 4 + h],
                    fmaf(a.z, sW[(4 * q + 2) * 4 + h],
                    fmaf(a.w, sW[(4 * q + 3) * 4 + h], sc[h]))));
        }
    }
#pragma unroll
    for (int h = 0; h < 4; h++) sc[h] = (sc[h] > 0.f) ? sc[h] : 0.2f * sc[h];
    int p = __ldg(&g_pos[e]);
    *(float4*)&g_sc[(size_t)p * 4] = make_float4(sc[0], sc[1], sc[2], sc[3]);
}

// ---------------- layer1 aggregation: persistent warps, fused softmax, prefetch ----------------
__global__ void __launch_bounds__(256) k_agg1(const float* __restrict__ eattr,
                                              const float* __restrict__ We, const float* __restrict__ et,
                                              const float* __restrict__ x, const float* __restrict__ res) {
    __shared__ float sEt[22 * 64];
    __shared__ float sWe[16 * 64];
    __shared__ float sRes[16 * 64];
    __shared__ float sWs[8 * 64];
    __shared__ float4 sAl[8][32];
    __shared__ int sS[8][32], sTt[8][32], sE[8][32];
    int tid = threadIdx.x, L = tid & 31, w = tid >> 5;
    for (int i = tid; i < 22 * 64; i += 256) sEt[i] = et[i];
    for (int i = tid; i < 16 * 64; i += 256) { sWe[i] = We[i]; sRes[i] = res[i]; }
    __syncthreads();

    const int H = L >> 3, hb = L >> 4;
    for (int n = blockIdx.x * 8 + w; n < NN; n += gridDim.x * 8) {
        int r0 = __ldg(&g_rowptr[n]), r1 = __ldg(&g_rowptr[n + 1]);

        float m[4] = {-3e38f, -3e38f, -3e38f, -3e38f}, dd[4] = {0.f, 0.f, 0.f, 0.f};
        for (int i = r0 + L; i < r1; i += 32) {
            float4 s = *(const float4*)&g_sc[(size_t)i * 4];
            float sv[4] = {s.x, s.y, s.z, s.w};
#pragma unroll
            for (int h = 0; h < 4; h++) {
                if (sv[h] > m[h]) { dd[h] *= __expf(m[h] - sv[h]); m[h] = sv[h]; }
                dd[h] += __expf(sv[h] - m[h]);
            }
        }
#pragma unroll
        for (int o = 16; o >= 1; o >>= 1) {
#pragma unroll
            for (int h = 0; h < 4; h++) {
                float mo = __shfl_xor_sync(0xffffffffu, m[h], o);
                float d_o = __shfl_xor_sync(0xffffffffu, dd[h], o);
                float mn = fmaxf(m[h], mo);
                dd[h] = dd[h] * __expf(m[h] - mn) + d_o * __expf(mo - mn);
                m[h] = mn;
            }
        }
        float inv[4];
#pragma unroll
        for (int h = 0; h < 4; h++) inv[h] = 1.f / (dd[h] + 1e-16f);

        float ax = 0.f, ay = 0.f;
        float w0 = 0.f, w1 = 0.f;
        for (int base = r0; base < r1; base += 32) {
            int nv = min(32, r1 - base);
            if (L < nv) {
                float4 s = *(const float4*)&g_sc[(size_t)(base + L) * 4];
                int2 mt = g_meta[base + L];
                sAl[w][L] = make_float4(__expf(s.x - m[0]) * inv[0], __expf(s.y - m[1]) * inv[1],
                                        __expf(s.z - m[2]) * inv[2], __expf(s.w - m[3]) * inv[3]);
                sS[w][L] = mt.x; sTt[w][L] = mt.y; sE[w][L] = g_eorig[base + L];
            }
            __syncwarp();
            int sj = sS[w][0], tj = sTt[w][0], ej = sE[w][0];
            float2 h2 = *(const float2*)&g_h[(size_t)sj * 64 + 2 * L];
            float ea = __ldg(&eattr[(size_t)ej * 16 + (L & 15)]);
            for (int j = 0; j < nv; j++) {
                float4 al = sAl[w][j];
                float2 ev = *(const float2*)&sEt[tj * 64 + 2 * L];
                float ah = (H == 0) ? al.x : ((H == 1) ? al.y : ((H == 2) ? al.z : al.w));
                ax = fmaf(ah, h2.x + ev.x, ax);
                ay = fmaf(ah, h2.y + ev.y, ay);
                float aw0 = hb ? al.y : al.x, aw1 = hb ? al.w : al.z;
                w0 = fmaf(aw0, ea, w0);
                w1 = fmaf(aw1, ea, w1);
                if (j + 1 < nv) {
                    sj = sS[w][j + 1]; tj = sTt[w][j + 1]; ej = sE[w][j + 1];
                    h2 = *(const float2*)&g_h[(size_t)sj * 64 + 2 * L];
                    ea = __ldg(&eattr[(size_t)ej * 16 + (L & 15)]);
                }
            }
            __syncwarp();
        }
        sWs[w * 64 + L] = w0;
        sWs[w * 64 + 32 + L] = w1;
        __syncwarp();
#pragma unroll
        for (int k = 0; k < 16; k++) {
            float wk = sWs[w * 64 + H * 16 + k];
            float2 we = *(const float2*)&sWe[k * 64 + 2 * L];
            ax = fmaf(wk, we.x, ax);
            ay = fmaf(wk, we.y, ay);
        }
        const float4* xp = (const float4*)(x + (size_t)n * 16);
        float4 xa = __ldg(xp), xb = __ldg(xp + 1), xc = __ldg(xp + 2), xd = __ldg(xp + 3);
        float xv[16] = {xa.x, xa.y, xa.z, xa.w, xb.x, xb.y, xb.z, xb.w,
                        xc.x, xc.y, xc.z, xc.w, xd.x, xd.y, xd.z, xd.w};
#pragma unroll
        for (int k = 0; k < 16; k++) {
            float2 rv = *(const float2*)&sRes[k * 64 + 2 * L];
            ax = fmaf(xv[k], rv.x, ax);
            ay = fmaf(xv[k], rv.y, ay);
        }
        *(float2*)&g_z1[(size_t)n * 64 + 2 * L] = make_float2(fmaxf(ax, 0.f), fmaxf(ay, 0.f));
        __syncwarp();
    }
}

// ---------------- build M2 [408 x 64] (pre-scaled by 0.25 for head mean) ----------------
__global__ void k_buildM2(const float* __restrict__ Wx2, const float* __restrict__ We2,
                          const float* __restrict__ et2) {
    int idx = blockIdx.x * blockDim.x + threadIdx.x;
    if (idx >= 408 * 64) return;
    int r = idx >> 6, c = idx & 63;
    float v;
    if (r < 256) {
        int h = r >> 6, k = r & 63;
        v = 0.25f * Wx2[k * 256 + h * 64 + c];
    } else if (r < 320) {
        int j = r - 256, h = j >> 4, k = j & 15;
        v = 0.25f * We2[k * 256 + h * 64 + c];
    } else {
        int j = r - 320, h = j / 22, t = j % 22;
        v = 0.25f * et2[t * 256 + h * 64 + c];
    }
    g_M2[idx] = v;
}

// ---------------- prep2: u2 = z1 + nt2[type]; ss2/sd2 via precomputed was2/wad2 ----------------
__global__ void k_prep2(const int* __restrict__ ntype, const float* __restrict__ nt2) {
    __shared__ float sNt[512], sWs[256], sWd[256];
    int tid = threadIdx.x;
    for (int i = tid; i < 512; i += 256) sNt[i] = nt2[i];
    if (tid < 256) { sWs[tid] = g_was2[tid]; sWd[tid] = g_wad2[tid]; }
    __syncthreads();
    int n = blockIdx.x * blockDim.x + tid;
    if (n >= NN) return;
    int t = __ldg(&ntype[n]);
    float u[64];
    const float4* zp = (const float4*)(g_z1 + (size_t)n * 64);
    float4* up = (float4*)(g_u2 + (size_t)n * 64);
#pragma unroll
    for (int q = 0; q < 16; q++) {
        float4 zv = zp[q];
        float4 nv = *(const float4*)&sNt[t * 64 + q * 4];
        u[q * 4 + 0] = zv.x + nv.x;
        u[q * 4 + 1] = zv.y + nv.y;
        u[q * 4 + 2] = zv.z + nv.z;
        u[q * 4 + 3] = zv.w + nv.w;
        up[q] = make_float4(u[q * 4], u[q * 4 + 1], u[q * 4 + 2], u[q * 4 + 3]);
    }
    float ss[4], sd[4];
#pragma unroll
    for (int h = 0; h < 4; h++) {
        float a = 0.f, b = 0.f;
#pragma unroll
        for (int k = 0; k < 64; k++) {
            a = fmaf(u[k], sWs[h * 64 + k], a);
            b = fmaf(u[k], sWd[h * 64 + k], b);
        }
        ss[h] = a; sd[h] = b;
    }
    *(float4*)&g_ss[n * 4] = make_float4(ss[0], ss[1], ss[2], ss[3]);
    *(float4*)&g_sd[n * 4] = make_float4(sd[0], sd[1], sd[2], sd[3]);
}

// ---------------- layer2 aggregation: warp-per-node, fused softmax, gathers u2 (L2-resident) ----------------
__global__ void __launch_bounds__(256) k_agg2(const float* __restrict__ eattr) {
    __shared__ float4 sAl[8][32];
    __shared__ int sS[8][32], sTt[8][32], sE[8][32];
    __shared__ float sHist[8][96];
    int tid = threadIdx.x, L = tid & 31, w = tid >> 5;
    int n = blockIdx.x * 8 + w;
    if (n >= NN) return;
    int r0 = __ldg(&g_rowptr[n]), r1 = __ldg(&g_rowptr[n + 1]);

    // fused warp-level online softmax over contiguous CSR scores
    float m[4] = {-3e38f, -3e38f, -3e38f, -3e38f}, dd[4] = {0.f, 0.f, 0.f, 0.f};
    for (int i = r0 + L; i < r1; i += 32) {
        float4 s = *(const float4*)&g_sc[(size_t)i * 4];
        float sv[4] = {s.x, s.y, s.z, s.w};
#pragma unroll
        for (int h = 0; h < 4; h++) {
            if (sv[h] > m[h]) { dd[h] *= __expf(m[h] - sv[h]); m[h] = sv[h]; }
            dd[h] += __expf(sv[h] - m[h]);
        }
    }
#pragma unroll
    for (int o = 16; o >= 1; o >>= 1) {
#pragma unroll
        for (int h = 0; h < 4; h++) {
            float mo = __shfl_xor_sync(0xffffffffu, m[h], o);
            float d_o = __shfl_xor_sync(0xffffffffu, dd[h], o);
            float mn = fmaxf(m[h], mo);
            dd[h] = dd[h] * __expf(m[h] - mn) + d_o * __expf(mo - mn);
            m[h] = mn;
        }
    }
    float inv[4];
#pragma unroll
    for (int h = 0; h < 4; h++) inv[h] = 1.f / (dd[h] + 1e-16f);

    for (int i = L; i < 88; i += 32) sHist[w][i] = 0.f;
    float y0x = 0.f, y0y = 0.f, y1x = 0.f, y1y = 0.f;
    float y2x = 0.f, y2y = 0.f, y3x = 0.f, y3y = 0.f;
    float e0 = 0.f, e1 = 0.f, e2 = 0.f, e3 = 0.f;
    __syncwarp();

    for (int base = r0; base < r1; base += 32) {
        int nv = min(32, r1 - base);
        if (L < nv) {
            float4 s = *(const float4*)&g_sc[(size_t)(base + L) * 4];
            int2 mt = g_meta[base + L];
            sAl[w][L] = make_float4(__expf(s.x - m[0]) * inv[0], __expf(s.y - m[1]) * inv[1],
                                    __expf(s.z - m[2]) * inv[2], __expf(s.w - m[3]) * inv[3]);
            sS[w][L] = mt.x; sTt[w][L] = mt.y; sE[w][L] = g_eorig[base + L];
        }
        __syncwarp();
        int sj = sS[w][0], tj = sTt[w][0], ej = sE[w][0];
        float2 u = *(const float2*)&g_u2[(size_t)sj * 64 + 2 * L];
        float ea = (L < 16) ? __ldg(&eattr[(size_t)ej * 16 + L]) : 0.f;
        for (int j = 0; j < nv; j++) {
            float4 al = sAl[w][j];
            y0x = fmaf(al.x, u.x, y0x); y0y = fmaf(al.x, u.y, y0y);
            y1x = fmaf(al.y, u.x, y1x); y1y = fmaf(al.y, u.y, y1y);
            y2x = fmaf(al.z, u.x, y2x); y2y = fmaf(al.z, u.y, y2y);
            y3x = fmaf(al.w, u.x, y3x); y3y = fmaf(al.w, u.y, y3y);
            e0 = fmaf(al.x, ea, e0); e1 = fmaf(al.y, ea, e1);
            e2 = fmaf(al.z, ea, e2); e3 = fmaf(al.w, ea, e3);
            if (L >= 16 && L < 20) {
                int h = L - 16;
                float a = (h == 0) ? al.x : ((h == 1) ? al.y : ((h == 2) ? al.z : al.w));
                sHist[w][h * 22 + tj] += a;
            }
            if (j + 1 < nv) {
                sj = sS[w][j + 1]; tj = sTt[w][j + 1]; ej = sE[w][j + 1];
                u = *(const float2*)&g_u2[(size_t)sj * 64 + 2 * L];
                ea = (L < 16) ? __ldg(&eattr[(size_t)ej * 16 + L]) : 0.f;
            }
        }
        __syncwarp();
    }
    size_t vb = (size_t)n * 408;
    *(float2*)&g_v2[vb + 0 * 64 + 2 * L] = make_float2(y0x, y0y);
    *(float2*)&g_v2[vb + 1 * 64 + 2 * L] = make_float2(y1x, y1y);
    *(float2*)&g_v2[vb + 2 * 64 + 2 * L] = make_float2(y2x, y2y);
    *(float2*)&g_v2[vb + 3 * 64 + 2 * L] = make_float2(y3x, y3y);
    if (L < 16) {
        g_v2[vb + 256 + L]      = e0;
        g_v2[vb + 256 + 16 + L] = e1;
        g_v2[vb + 256 + 32 + L] = e2;
        g_v2[vb + 256 + 48 + L] = e3;
    }
    for (int i = L; i < 88; i += 32) g_v2[vb + 320 + i] = sHist[w][i];
}

// ---------------- gemm2: zout = z1 + v2 @ M2 ; fp32 tiled, B resident, A transposed ----------------
__global__ void __launch_bounds__(256) k_gemm2(float* __restrict__ zout) {
    extern __shared__ float sm[];
    float* sB = sm;              // 408*64
    float* sAT = sB + 408 * 64;  // [k=408][row 36] transposed

    int tid = threadIdx.x;
    int tx = tid & 15, ty = tid >> 4;
    int c0 = tx * 4, r0 = ty * 2;

    for (int i = tid; i < 6528; i += 256)
        *(float4*)&sB[i * 4] = ((const float4*)g_M2)[i];

    const int NT = NN / 32;  // 3125 exact
    for (int tile = blockIdx.x; tile < NT; tile += gridDim.x) {
        __syncthreads();
        for (int i = tid; i < 32 * 102; i += 256) {
            int r = i / 102, q = i % 102;
            float4 v = ((const float4*)&g_v2[(size_t)(tile * 32 + r) * 408])[q];
            sAT[(4 * q + 0) * 36 + r] = v.x;
            sAT[(4 * q + 1) * 36 + r] = v.y;
            sAT[(4 * q + 2) * 36 + r] = v.z;
            sAT[(4 * q + 3) * 36 + r] = v.w;
        }
        __syncthreads();

        float4 acc0 = make_float4(0.f, 0.f, 0.f, 0.f);
        float4 acc1 = make_float4(0.f, 0.f, 0.f, 0.f);
#pragma unroll 4
        for (int k = 0; k < 408; k++) {
            float4 b = *(const float4*)&sB[k * 64 + c0];
            float a0 = sAT[k * 36 + r0];
            float a1 = sAT[k * 36 + r0 + 1];
            acc0.x = fmaf(a0, b.x, acc0.x); acc0.y = fmaf(a0, b.y, acc0.y);
            acc0.z = fmaf(a0, b.z, acc0.z); acc0.w = fmaf(a0, b.w, acc0.w);
            acc1.x = fmaf(a1, b.x, acc1.x); acc1.y = fmaf(a1, b.y, acc1.y);
            acc1.z = fmaf(a1, b.z, acc1.z); acc1.w = fmaf(a1, b.w, acc1.w);
        }
        int gr = tile * 32 + r0;
        float4 z0 = *(const float4*)&g_z1[(size_t)gr * 64 + c0];
        float4 z1 = *(const float4*)&g_z1[(size_t)(gr + 1) * 64 + c0];
        float4 o0 = make_float4(z0.x + acc0.x, z0.y + acc0.y, z0.z + acc0.z, z0.w + acc0.w);
        float4 o1 = make_float4(z1.x + acc1.x, z1.y + acc1.y, z1.z + acc1.z, z1.w + acc1.w);
        *(float4*)&zout[(size_t)gr * 64 + c0] = o0;
        *(float4*)&zout[(size_t)(gr + 1) * 64 + c0] = o1;
    }
}

// ---------------- decoder: persistent tiled fp32 GEMM, W1 resident ----------------
__global__ void __launch_bounds__(256) k_dec(const int* __restrict__ eli, const float* __restrict__ z,
                                             const float* __restrict__ W1, const float* __restrict__ b1,
                                             const float* __restrict__ W2, const float* __restrict__ b2,
                                             float* __restrict__ pred) {
    extern __shared__ float sm[];
    float* sA = sm;                 // 64*132
    float* sB = sA + 64 * 132;      // 128*64
    int*   sR = (int*)(sB + 8192);  // 64
    int*   sC = sR + 64;            // 64
    float* sb1 = (float*)(sC + 64); // 64
    float* sw2 = sb1 + 64;          // 64

    int tid = threadIdx.x;
    if (tid < 64) { sb1[tid] = b1[tid]; sw2[tid] = W2[tid]; }
    for (int i = tid; i < 2048; i += 256)
        *(float4*)&sB[i * 4] = *(const float4*)&W1[(size_t)i * 4];

    int tx = tid & 15, ty = tid >> 4;
    int c0 = tx * 4, r0 = ty * 4;
    float bb = __ldg(&b2[0]);

    const int NT = ELN / 64;
    for (int tile = blockIdx.x; tile < NT; tile += gridDim.x) {
        int ebase = tile * 64;
        __syncthreads();
        if (tid < 64) sR[tid] = __ldg(&eli[ebase + tid]);
        else if (tid < 128) sC[tid - 64] = __ldg(&eli[ELN + ebase + tid - 64]);
        __syncthreads();
        for (int i = tid; i < 2048; i += 256) {
            int e = i >> 5, sg = i & 31;
            int node = (sg < 16) ? sR[e] : sC[e];
            float4 v = *(const float4*)&z[(size_t)node * 64 + (sg & 15) * 4];
            *(float4*)&sA[e * 132 + sg * 4] = v;
        }
        __syncthreads();

        float4 acc[4];
#pragma unroll
        for (int i = 0; i < 4; i++) acc[i] = make_float4(0.f, 0.f, 0.f, 0.f);

#pragma unroll 4
        for (int k = 0; k < 128; k++) {
            float4 b = *(const float4*)&sB[k * 64 + c0];
#pragma unroll
            for (int i = 0; i < 4; i++) {
                float a = sA[(r0 + i) * 132 + k];
                acc[i].x = fmaf(a, b.x, acc[i].x);
                acc[i].y = fmaf(a, b.y, acc[i].y);
                acc[i].z = fmaf(a, b.z, acc[i].z);
                acc[i].w = fmaf(a, b.w, acc[i].w);
            }
        }

        float p[4];
#pragma unroll
        for (int i = 0; i < 4; i++) {
            float hx = fmaxf(acc[i].x + sb1[c0],     0.f);
            float hy = fmaxf(acc[i].y + sb1[c0 + 1], 0.f);
            float hz = fmaxf(acc[i].z + sb1[c0 + 2], 0.f);
            float hw = fmaxf(acc[i].w + sb1[c0 + 3], 0.f);
            p[i] = hx * sw2[c0] + hy * sw2[c0 + 1] + hz * sw2[c0 + 2] + hw * sw2[c0 + 3];
        }
#pragma unroll
        for (int o = 1; o < 16; o <<= 1) {
#pragma unroll
            for (int i = 0; i < 4; i++) p[i] += __shfl_xor_sync(0xffffffffu, p[i], o);
        }
        if (tx == 0) {
#pragma unroll
            for (int i = 0; i < 4; i++) pred[ebase + r0 + i] = p[i] + bb;
        }
    }
}

// ---------------- launch ----------------
extern "C" void kernel_launch(void* const* d_in, const int* in_sizes, int n_in,
                              void* d_out, int out_size) {
    const float* x     = (const float*)d_in[0];
    const int*   ei    = (const int*)d_in[1];
    const int*   ntype = (const int*)d_in[2];
    const float* eattr = (const float*)d_in[3];
    const int*   etype = (const int*)d_in[4];
    const int*   eli   = (const int*)d_in[5];
    const float* Wx1   = (const float*)d_in[6];
    const float* We1   = (const float*)d_in[7];
    const float* nt1   = (const float*)d_in[8];
    const float* et1   = (const float*)d_in[9];
    const float* as1   = (const float*)d_in[10];
    const float* ad1   = (const float*)d_in[11];
    const float* ae1   = (const float*)d_in[12];
    const float* res1  = (const float*)d_in[13];
    const float* Wx2   = (const float*)d_in[14];
    const float* We2   = (const float*)d_in[15];
    const float* nt2   = (const float*)d_in[16];
    const float* et2   = (const float*)d_in[17];
    const float* as2   = (const float*)d_in[18];
    const float* ad2   = (const float*)d_in[19];
    const float* ae2   = (const float*)d_in[20];
    const float* W1    = (const float*)d_in[21];
    const float* b1    = (const float*)d_in[22];
    const float* W2    = (const float*)d_in[23];
    const float* b2    = (const float*)d_in[24];

    float* pred = (float*)d_out;
    float* zout = pred + ELN;

    size_t smG2 = (size_t)(408 * 64 + 408 * 36) * sizeof(float);
    size_t smD  = (size_t)(64 * 132 + 128 * 64 + 64 + 64 + 64 + 64) * sizeof(float);
    static bool attr_done = false;
    if (!attr_done) {
        cudaFuncSetAttribute((const void*)k_gemm2, cudaFuncAttributeMaxDynamicSharedMemorySize, (int)smG2);
        cudaFuncSetAttribute((const void*)k_dec, cudaFuncAttributeMaxDynamicSharedMemorySize, (int)smD);
        attr_done = true;
    }

    // CSR build + precompute
    k_count<<<(EE + 255) / 256, 256>>>(ei);
    k_scanfuse<<<1, 1024>>>(We1, ae1, et1, We2, ae2, et2, Wx2, as2, ad2);
    k_fill<<<(EE + 255) / 256, 256>>>(ei, etype);

    // layer 1 (k_proj1 stays 4th launch -> comparable profiled slot)
    k_proj1<<<592, 256>>>(x, ntype, nt1, Wx1, as1, ad1);
    k_score<1><<<(EE + 255) / 256, 256>>>(ei, eattr, etype);
    k_agg1<<<1184, 256>>>(eattr, We1, et1, x, res1);

    // layer 2
    k_buildM2<<<102, 256>>>(Wx2, We2, et2);
    k_prep2<<<(NN + 255) / 256, 256>>>(ntype, nt2);
    k_score<2><<<(EE + 255) / 256, 256>>>(ei, eattr, etype);
    k_agg2<<<(NN + 7) / 8, 256>>>(eattr);
    k_gemm2<<<148, 256, smG2>>>(zout);

    // decoder
    k_dec<<<592, 256, smD>>>(eli, zout, W1, b1, W2, b2, pred);
}

// round 12
// speedup vs baseline: 1.3414x; 1.3414x over previous
#include <cuda_runtime.h>
#include <cuda_fp16.h>
#include <cstdint>

#define NN 100000
#define EE 600000
#define ELN 200000

// ---------------- device scratch ----------------
__device__ float  g_h[(size_t)NN * 64];     // layer1 node projections (fp32)
__device__ __half g_h2h[(size_t)NN * 256];  // layer2 node projections (fp16)
__device__ float  g_z1[(size_t)NN * 64];    // layer1 output
__device__ float  g_sc[(size_t)EE * 4];     // CSR-ordered scores
__device__ float  g_ss[NN * 4];
__device__ float  g_sd[NN * 4];
__device__ int    g_cnt[NN];
__device__ int    g_rowptr[NN + 1];
__device__ int    g_cur[NN];
__device__ int    g_pos[EE];                // edge -> CSR slot
__device__ int2   g_meta[EE];               // CSR slot -> (src, etype)
__device__ int    g_eorig[EE];              // CSR slot -> original edge id
__device__ float  g_wae1[64], g_tae1[88];
__device__ float  g_wae2[64], g_tae2[88];

// ---------------- CSR build ----------------
__global__ void k_count(const int* __restrict__ ei) {
    int e = blockIdx.x * blockDim.x + threadIdx.x;
    if (e < EE) atomicAdd(&g_cnt[ei[EE + e]], 1);
}

__global__ void k_scanfuse(const float* __restrict__ We1, const float* __restrict__ ae1,
                           const float* __restrict__ et1,
                           const float* __restrict__ We2, const float* __restrict__ ae2,
                           const float* __restrict__ et2) {
    __shared__ int sp[1024];
    int tid = threadIdx.x;
    if (tid < 64) {
        int k = tid >> 2, h = tid & 3;
        float s = 0.f;
        for (int d = 0; d < 16; d++) s += We1[k * 64 + h * 16 + d] * ae1[h * 16 + d];
        g_wae1[k * 4 + h] = s;
        float s2 = 0.f;
        for (int d = 0; d < 64; d++) s2 += We2[k * 256 + h * 64 + d] * ae2[h * 64 + d];
        g_wae2[k * 4 + h] = s2;
    }
    if (tid < 88) {
        int t = tid >> 2, h = tid & 3;
        float s = 0.f;
        for (int d = 0; d < 16; d++) s += et1[t * 64 + h * 16 + d] * ae1[h * 16 + d];
        g_tae1[t * 4 + h] = s;
        float s2 = 0.f;
        for (int d = 0; d < 64; d++) s2 += et2[t * 256 + h * 64 + d] * ae2[h * 64 + d];
        g_tae2[t * 4 + h] = s2;
    }
    const int chunk = (NN + 1023) >> 10;
    int st = tid * chunk;
    int en = st + chunk; if (en > NN) en = NN;
    int s = 0;
    for (int i = st; i < en; i++) s += g_cnt[i];
    sp[tid] = s;
    __syncthreads();
    for (int o = 1; o < 1024; o <<= 1) {
        int v = (tid >= o) ? sp[tid - o] : 0;
        __syncthreads();
        sp[tid] += v;
        __syncthreads();
    }
    int b = sp[tid] - s;
    for (int i = st; i < en; i++) {
        g_rowptr[i] = b; g_cur[i] = b; b += g_cnt[i];
        g_cnt[i] = 0;   // re-zero for next replay (graph-invariant)
    }
    if (tid == 1023) g_rowptr[NN] = sp[1023];
}

__global__ void k_fill(const int* __restrict__ ei, const int* __restrict__ etype) {
    int e = blockIdx.x * blockDim.x + threadIdx.x;
    if (e < EE) {
        int d = ei[EE + e];
        int p = atomicAdd(&g_cur[d], 1);
        g_pos[e] = p;
        g_meta[p] = make_int2(ei[e], etype[e]);
        g_eorig[p] = e;
    }
}

// ---------------- layer1 node projection: persistent, Wx in registers ----------------
__global__ void __launch_bounds__(256) k_proj1(const float* __restrict__ x, const int* __restrict__ ntype,
                                               const float* __restrict__ nt, const float* __restrict__ Wx,
                                               const float* __restrict__ a_s, const float* __restrict__ a_d) {
    __shared__ float sNt[8 * 16];
    int tid = threadIdx.x, L = tid & 31, w = tid >> 5;
    for (int i = tid; i < 128; i += 256) sNt[i] = nt[i];

    float W0[16], W1r[16];
#pragma unroll
    for (int k = 0; k < 16; k++) {
        W0[k]  = __ldg(&Wx[k * 64 + L]);
        W1r[k] = __ldg(&Wx[k * 64 + 32 + L]);
    }
    float as0 = __ldg(&a_s[L]), as1 = __ldg(&a_s[32 + L]);
    float ad0 = __ldg(&a_d[L]), ad1 = __ldg(&a_d[32 + L]);
    __syncthreads();

    int nwarps = gridDim.x * 8;
    for (int n = blockIdx.x * 8 + w; n < NN; n += nwarps) {
        int t = __ldg(&ntype[n]);
        float xv = 0.f;
        if (L < 16) xv = __ldg(&x[(size_t)n * 16 + L]) + sNt[t * 16 + L];
        float acc0 = 0.f, acc1 = 0.f;
#pragma unroll
        for (int k = 0; k < 16; k++) {
            float xk = __shfl_sync(0xffffffffu, xv, k);
            acc0 = fmaf(xk, W0[k], acc0);
            acc1 = fmaf(xk, W1r[k], acc1);
        }
        g_h[(size_t)n * 64 + L] = acc0;
        g_h[(size_t)n * 64 + 32 + L] = acc1;

        float pa = acc0 * as0, pb = acc1 * as1;
        float qa = acc0 * ad0, qb = acc1 * ad1;
#pragma unroll
        for (int o = 8; o >= 1; o >>= 1) {
            pa += __shfl_xor_sync(0xffffffffu, pa, o);
            pb += __shfl_xor_sync(0xffffffffu, pb, o);
            qa += __shfl_xor_sync(0xffffffffu, qa, o);
            qb += __shfl_xor_sync(0xffffffffu, qb, o);
        }
        if (L == 0)  { g_ss[n * 4 + 0] = pa; g_ss[n * 4 + 2] = pb; g_sd[n * 4 + 0] = qa; g_sd[n * 4 + 2] = qb; }
        if (L == 16) { g_ss[n * 4 + 1] = pa; g_ss[n * 4 + 3] = pb; g_sd[n * 4 + 1] = qa; g_sd[n * 4 + 3] = qb; }
    }
}

// ---------------- edge scores (raw, post-leaky), scattered to CSR slots ----------------
template <int LAYER>
__global__ void k_score(const int* __restrict__ ei, const float* __restrict__ eattr,
                        const int* __restrict__ etype) {
    __shared__ float sW[64];
    __shared__ float sT[88];
    const float* wae = (LAYER == 1) ? g_wae1 : g_wae2;
    const float* tae = (LAYER == 1) ? g_tae1 : g_tae2;
    if (threadIdx.x < 64) sW[threadIdx.x] = wae[threadIdx.x];
    if (threadIdx.x < 88) sT[threadIdx.x] = tae[threadIdx.x];
    __syncthreads();

    int e = blockIdx.x * blockDim.x + threadIdx.x;
    if (e >= EE) return;
    int s = ei[e], d = ei[EE + e], t = etype[e];
    float sc[4];
#pragma unroll
    for (int h = 0; h < 4; h++)
        sc[h] = g_ss[s * 4 + h] + g_sd[d * 4 + h] + sT[t * 4 + h];

    const float4* ea = (const float4*)(eattr + (size_t)e * 16);
#pragma unroll
    for (int q = 0; q < 4; q++) {
        float4 a = __ldg(ea + q);
#pragma unroll
        for (int h = 0; h < 4; h++) {
            sc[h] = fmaf(a.x, sW[(4 * q + 0) * 4 + h],
                    fmaf(a.y, sW[(4 * q + 1) * 4 + h],
                    fmaf(a.z, sW[(4 * q + 2) * 4 + h],
                    fmaf(a.w, sW[(4 * q + 3) * 4 + h], sc[h]))));
        }
    }
#pragma unroll
    for (int h = 0; h < 4; h++) sc[h] = (sc[h] > 0.f) ? sc[h] : 0.2f * sc[h];
    int p = __ldg(&g_pos[e]);
    *(float4*)&g_sc[(size_t)p * 4] = make_float4(sc[0], sc[1], sc[2], sc[3]);
}

// ---------------- layer1 aggregation: persistent warps, fused softmax, prefetch ----------------
__global__ void __launch_bounds__(256) k_agg1(const float* __restrict__ eattr,
                                              const float* __restrict__ We, const float* __restrict__ et,
                                              const float* __restrict__ x, const float* __restrict__ res) {
    __shared__ float sEt[22 * 64];
    __shared__ float sWe[16 * 64];
    __shared__ float sRes[16 * 64];
    __shared__ float sWs[8 * 64];
    __shared__ float4 sAl[8][32];
    __shared__ int sS[8][32], sTt[8][32], sE[8][32];
    int tid = threadIdx.x, L = tid & 31, w = tid >> 5;
    for (int i = tid; i < 22 * 64; i += 256) sEt[i] = et[i];
    for (int i = tid; i < 16 * 64; i += 256) { sWe[i] = We[i]; sRes[i] = res[i]; }
    __syncthreads();

    const int H = L >> 3, hb = L >> 4;
    for (int n = blockIdx.x * 8 + w; n < NN; n += gridDim.x * 8) {
        int r0 = __ldg(&g_rowptr[n]), r1 = __ldg(&g_rowptr[n + 1]);

        float m[4] = {-3e38f, -3e38f, -3e38f, -3e38f}, dd[4] = {0.f, 0.f, 0.f, 0.f};
        for (int i = r0 + L; i < r1; i += 32) {
            float4 s = *(const float4*)&g_sc[(size_t)i * 4];
            float sv[4] = {s.x, s.y, s.z, s.w};
#pragma unroll
            for (int h = 0; h < 4; h++) {
                if (sv[h] > m[h]) { dd[h] *= __expf(m[h] - sv[h]); m[h] = sv[h]; }
                dd[h] += __expf(sv[h] - m[h]);
            }
        }
#pragma unroll
        for (int o = 16; o >= 1; o >>= 1) {
#pragma unroll
            for (int h = 0; h < 4; h++) {
                float mo = __shfl_xor_sync(0xffffffffu, m[h], o);
                float d_o = __shfl_xor_sync(0xffffffffu, dd[h], o);
                float mn = fmaxf(m[h], mo);
                dd[h] = dd[h] * __expf(m[h] - mn) + d_o * __expf(mo - mn);
                m[h] = mn;
            }
        }
        float inv[4];
#pragma unroll
        for (int h = 0; h < 4; h++) inv[h] = 1.f / (dd[h] + 1e-16f);

        float ax = 0.f, ay = 0.f;
        float w0 = 0.f, w1 = 0.f;
        for (int base = r0; base < r1; base += 32) {
            int nv = min(32, r1 - base);
            if (L < nv) {
                float4 s = *(const float4*)&g_sc[(size_t)(base + L) * 4];
                int2 mt = g_meta[base + L];
                sAl[w][L] = make_float4(__expf(s.x - m[0]) * inv[0], __expf(s.y - m[1]) * inv[1],
                                        __expf(s.z - m[2]) * inv[2], __expf(s.w - m[3]) * inv[3]);
                sS[w][L] = mt.x; sTt[w][L] = mt.y; sE[w][L] = g_eorig[base + L];
            }
            __syncwarp();
            int sj = sS[w][0], tj = sTt[w][0], ej = sE[w][0];
            float2 h2 = *(const float2*)&g_h[(size_t)sj * 64 + 2 * L];
            float ea = __ldg(&eattr[(size_t)ej * 16 + (L & 15)]);
            for (int j = 0; j < nv; j++) {
                float4 al = sAl[w][j];
                float2 ev = *(const float2*)&sEt[tj * 64 + 2 * L];
                float ah = (H == 0) ? al.x : ((H == 1) ? al.y : ((H == 2) ? al.z : al.w));
                ax = fmaf(ah, h2.x + ev.x, ax);
                ay = fmaf(ah, h2.y + ev.y, ay);
                float aw0 = hb ? al.y : al.x, aw1 = hb ? al.w : al.z;
                w0 = fmaf(aw0, ea, w0);
                w1 = fmaf(aw1, ea, w1);
                if (j + 1 < nv) {
                    sj = sS[w][j + 1]; tj = sTt[w][j + 1]; ej = sE[w][j + 1];
                    h2 = *(const float2*)&g_h[(size_t)sj * 64 + 2 * L];
                    ea = __ldg(&eattr[(size_t)ej * 16 + (L & 15)]);
                }
            }
            __syncwarp();
        }
        sWs[w * 64 + L] = w0;
        sWs[w * 64 + 32 + L] = w1;
        __syncwarp();
#pragma unroll
        for (int k = 0; k < 16; k++) {
            float wk = sWs[w * 64 + H * 16 + k];
            float2 we = *(const float2*)&sWe[k * 64 + 2 * L];
            ax = fmaf(wk, we.x, ax);
            ay = fmaf(wk, we.y, ay);
        }
        const float4* xp = (const float4*)(x + (size_t)n * 16);
        float4 xa = __ldg(xp), xb = __ldg(xp + 1), xc = __ldg(xp + 2), xd = __ldg(xp + 3);
        float xv[16] = {xa.x, xa.y, xa.z, xa.w, xb.x, xb.y, xb.z, xb.w,
                        xc.x, xc.y, xc.z, xc.w, xd.x, xd.y, xd.z, xd.w};
#pragma unroll
        for (int k = 0; k < 16; k++) {
            float2 rv = *(const float2*)&sRes[k * 64 + 2 * L];
            ax = fmaf(xv[k], rv.x, ax);
            ay = fmaf(xv[k], rv.y, ay);
        }
        *(float2*)&g_z1[(size_t)n * 64 + 2 * L] = make_float2(fmaxf(ax, 0.f), fmaxf(ay, 0.f));
        __syncwarp();
    }
}

// ---------------- layer2 projection: tiled fp32 GEMM + fused ss/sd, h stored fp16 ----------------
__global__ void __launch_bounds__(256) k_proj2(const int* __restrict__ ntype, const float* __restrict__ nt,
                                               const float* __restrict__ Wx,
                                               const float* __restrict__ a_s, const float* __restrict__ a_d) {
    extern __shared__ float sm[];
    float* sA = sm;              // 128*68
    float* sB = sA + 128 * 68;   // 64*64
    float* sNt = sB + 4096;      // 8*64
    float* sAs = sNt + 512;      // 64
    float* sAd = sAs + 64;       // 64
    int*   sTy = (int*)(sAd + 64); // 128

    int tid = threadIdx.x;
    int by = blockIdx.y;
    int rbase = blockIdx.x * 128;

    for (int i = tid; i < 512; i += 256) sNt[i] = nt[i];
    if (tid < 64) { sAs[tid] = a_s[by * 64 + tid]; sAd[tid] = a_d[by * 64 + tid]; }
    if (tid < 128) { int r = rbase + tid; sTy[tid] = (r < NN) ? ntype[r] : 0; }
    __syncthreads();

    for (int i = tid; i < 1024; i += 256) {
        int k = i >> 4, cg = i & 15;
        float4 v = *(const float4*)&Wx[(size_t)k * 256 + by * 64 + cg * 4];
        *(float4*)&sB[k * 64 + cg * 4] = v;
    }
    for (int i = tid; i < 2048; i += 256) {
        int r = i >> 4, sg = i & 15;
        int gr = rbase + r;
        float4 v = make_float4(0.f, 0.f, 0.f, 0.f);
        if (gr < NN) {
            v = *(const float4*)&g_z1[(size_t)gr * 64 + sg * 4];
            float4 nv = *(const float4*)&sNt[sTy[r] * 64 + sg * 4];
            v.x += nv.x; v.y += nv.y; v.z += nv.z; v.w += nv.w;
        }
        *(float4*)&sA[r * 68 + sg * 4] = v;
    }
    __syncthreads();

    int tx = tid & 15, ty = tid >> 4;
    int c0 = tx * 4, r0 = ty * 8;
    float4 acc[8];
#pragma unroll
    for (int i = 0; i < 8; i++) acc[i] = make_float4(0.f, 0.f, 0.f, 0.f);

#pragma unroll 4
    for (int k = 0; k < 64; k++) {
        float4 b = *(const float4*)&sB[k * 64 + c0];
#pragma unroll
        for (int i = 0; i < 8; i++) {
            float a = sA[(r0 + i) * 68 + k];
            acc[i].x = fmaf(a, b.x, acc[i].x);
            acc[i].y = fmaf(a, b.y, acc[i].y);
            acc[i].z = fmaf(a, b.z, acc[i].z);
            acc[i].w = fmaf(a, b.w, acc[i].w);
        }
    }

    float ps[8], pd[8];
#pragma unroll
    for (int i = 0; i < 8; i++) {
        int gr = rbase + r0 + i;
        if (gr < NN) {
            __half2 lo = __floats2half2_rn(acc[i].x, acc[i].y);
            __half2 hi = __floats2half2_rn(acc[i].z, acc[i].w);
            uint2 packed;
            packed.x = *(unsigned*)&lo;
            packed.y = *(unsigned*)&hi;
            *(uint2*)&g_h2h[(size_t)gr * 256 + by * 64 + c0] = packed;
        }
        ps[i] = acc[i].x * sAs[c0] + acc[i].y * sAs[c0 + 1] + acc[i].z * sAs[c0 + 2] + acc[i].w * sAs[c0 + 3];
        pd[i] = acc[i].x * sAd[c0] + acc[i].y * sAd[c0 + 1] + acc[i].z * sAd[c0 + 2] + acc[i].w * sAd[c0 + 3];
    }
#pragma unroll
    for (int o = 1; o < 16; o <<= 1) {
#pragma unroll
        for (int i = 0; i < 8; i++) {
            ps[i] += __shfl_xor_sync(0xffffffffu, ps[i], o);
            pd[i] += __shfl_xor_sync(0xffffffffu, pd[i], o);
        }
    }
    if (tx == 0) {
#pragma unroll
        for (int i = 0; i < 8; i++) {
            int gr = rbase + r0 + i;
            if (gr < NN) { g_ss[gr * 4 + by] = ps[i]; g_sd[gr * 4 + by] = pd[i]; }
        }
    }
}

// ---------------- layer2 aggregation: persistent warps, fused softmax, fp16 h gathers ----------------
__global__ void __launch_bounds__(256) k_agg2(const float* __restrict__ eattr,
                                              const float* __restrict__ We, const float* __restrict__ et,
                                              float* __restrict__ zout) {
    __shared__ float4 sEt[22 * 64];
    __shared__ float4 sWe[16 * 64];
    __shared__ float  sWs[8 * 64];
    __shared__ float4 sAl[8][32];
    __shared__ int sS[8][32], sTt[8][32], sE[8][32];
    int tid = threadIdx.x, L = tid & 31, w = tid >> 5;
    for (int i = tid; i < 22 * 64; i += 256) sEt[i] = *(const float4*)&et[(size_t)i * 4];
    for (int i = tid; i < 16 * 64; i += 256) sWe[i] = *(const float4*)&We[(size_t)i * 4];
    __syncthreads();

    const int hb = L >> 4;
    for (int n = blockIdx.x * 8 + w; n < NN; n += gridDim.x * 8) {
        int r0 = __ldg(&g_rowptr[n]), r1 = __ldg(&g_rowptr[n + 1]);

        float m[4] = {-3e38f, -3e38f, -3e38f, -3e38f}, dd[4] = {0.f, 0.f, 0.f, 0.f};
        for (int i = r0 + L; i < r1; i += 32) {
            float4 s = *(const float4*)&g_sc[(size_t)i * 4];
            float sv[4] = {s.x, s.y, s.z, s.w};
#pragma unroll
            for (int h = 0; h < 4; h++) {
                if (sv[h] > m[h]) { dd[h] *= __expf(m[h] - sv[h]); m[h] = sv[h]; }
                dd[h] += __expf(sv[h] - m[h]);
            }
        }
#pragma unroll
        for (int o = 16; o >= 1; o >>= 1) {
#pragma unroll
            for (int h = 0; h < 4; h++) {
                float mo = __shfl_xor_sync(0xffffffffu, m[h], o);
                float d_o = __shfl_xor_sync(0xffffffffu, dd[h], o);
                float mn = fmaxf(m[h], mo);
                dd[h] = dd[h] * __expf(m[h] - mn) + d_o * __expf(mo - mn);
                m[h] = mn;
            }
        }
        float inv[4];
#pragma unroll
        for (int h = 0; h < 4; h++) inv[h] = 1.f / (dd[h] + 1e-16f);

        float4 acc0 = make_float4(0.f, 0.f, 0.f, 0.f);
        float4 acc1 = make_float4(0.f, 0.f, 0.f, 0.f);
        float w0 = 0.f, w1 = 0.f;

        for (int base = r0; base < r1; base += 32) {
            int nv = min(32, r1 - base);
            if (L < nv) {
                float4 s = *(const float4*)&g_sc[(size_t)(base + L) * 4];
                int2 mt = g_meta[base + L];
                sAl[w][L] = make_float4(__expf(s.x - m[0]) * inv[0], __expf(s.y - m[1]) * inv[1],
                                        __expf(s.z - m[2]) * inv[2], __expf(s.w - m[3]) * inv[3]);
                sS[w][L] = mt.x; sTt[w][L] = mt.y; sE[w][L] = g_eorig[base + L];
            }
            __syncwarp();
            int sj = sS[w][0], tj = sTt[w][0], ej = sE[w][0];
            uint2 raw0 = *(const uint2*)&g_h2h[(size_t)sj * 256 + 4 * L];
            uint2 raw1 = *(const uint2*)&g_h2h[(size_t)sj * 256 + 128 + 4 * L];
            float ea = __ldg(&eattr[(size_t)ej * 16 + (L & 15)]);
            for (int j = 0; j < nv; j++) {
                float4 al = sAl[w][j];
                float2 h0a = __half22float2(*(__half2*)&raw0.x);
                float2 h0b = __half22float2(*(__half2*)&raw0.y);
                float2 h1a = __half22float2(*(__half2*)&raw1.x);
                float2 h1b = __half22float2(*(__half2*)&raw1.y);
                float4 e0 = sEt[tj * 64 + L];
                float4 e1 = sEt[tj * 64 + 32 + L];
                float aA = hb ? al.y : al.x;
                float aB = hb ? al.w : al.z;
                acc0.x = fmaf(aA, h0a.x + e0.x, acc0.x);
                acc0.y = fmaf(aA, h0a.y + e0.y, acc0.y);
                acc0.z = fmaf(aA, h0b.x + e0.z, acc0.z);
                acc0.w = fmaf(aA, h0b.y + e0.w, acc0.w);
                acc1.x = fmaf(aB, h1a.x + e1.x, acc1.x);
                acc1.y = fmaf(aB, h1a.y + e1.y, acc1.y);
                acc1.z = fmaf(aB, h1b.x + e1.z, acc1.z);
                acc1.w = fmaf(aB, h1b.y + e1.w, acc1.w);
                w0 = fmaf(aA, ea, w0);
                w1 = fmaf(aB, ea, w1);
                if (j + 1 < nv) {
                    sj = sS[w][j + 1]; tj = sTt[w][j + 1]; ej = sE[w][j + 1];
                    raw0 = *(const uint2*)&g_h2h[(size_t)sj * 256 + 4 * L];
                    raw1 = *(const uint2*)&g_h2h[(size_t)sj * 256 + 128 + 4 * L];
                    ea = __ldg(&eattr[(size_t)ej * 16 + (L & 15)]);
                }
            }
            __syncwarp();
        }
        sWs[w * 64 + L] = w0;
        sWs[w * 64 + 32 + L] = w1;
        __syncwarp();

        const int H0i = hb, H1i = 2 + hb;
#pragma unroll
        for (int k = 0; k < 16; k++) {
            float k0 = sWs[w * 64 + H0i * 16 + k];
            float k1 = sWs[w * 64 + H1i * 16 + k];
            float4 we0 = sWe[k * 64 + L];
            float4 we1 = sWe[k * 64 + 32 + L];
            acc0.x = fmaf(k0, we0.x, acc0.x); acc0.y = fmaf(k0, we0.y, acc0.y);
            acc0.z = fmaf(k0, we0.z, acc0.z); acc0.w = fmaf(k0, we0.w, acc0.w);
            acc1.x = fmaf(k1, we1.x, acc1.x); acc1.y = fmaf(k1, we1.y, acc1.y);
            acc1.z = fmaf(k1, we1.z, acc1.z); acc1.w = fmaf(k1, we1.w, acc1.w);
        }
        float4 sm4;
        sm4.x = acc0.x + acc1.x; sm4.y = acc0.y + acc1.y;
        sm4.z = acc0.z + acc1.z; sm4.w = acc0.w + acc1.w;
        sm4.x += __shfl_xor_sync(0xffffffffu, sm4.x, 16);
        sm4.y += __shfl_xor_sync(0xffffffffu, sm4.y, 16);
        sm4.z += __shfl_xor_sync(0xffffffffu, sm4.z, 16);
        sm4.w += __shfl_xor_sync(0xffffffffu, sm4.w, 16);
        if (L < 16) {
            float4 z1v = *(const float4*)&g_z1[(size_t)n * 64 + 4 * L];
            float4 o;
            o.x = z1v.x + 0.25f * sm4.x;
            o.y = z1v.y + 0.25f * sm4.y;
            o.z = z1v.z + 0.25f * sm4.z;
            o.w = z1v.w + 0.25f * sm4.w;
            *(float4*)&zout[(size_t)n * 64 + 4 * L] = o;
        }
        __syncwarp();
    }
}

// ---------------- decoder: persistent tiled fp32 GEMM, W1 resident ----------------
__global__ void __launch_bounds__(256) k_dec(const int* __restrict__ eli, const float* __restrict__ z,
                                             const float* __restrict__ W1, const float* __restrict__ b1,
                                             const float* __restrict__ W2, const float* __restrict__ b2,
                                             float* __restrict__ pred) {
    extern __shared__ float sm[];
    float* sA = sm;                 // 64*132
    float* sB = sA + 64 * 132;      // 128*64
    int*   sR = (int*)(sB + 8192);  // 64
    int*   sC = sR + 64;            // 64
    float* sb1 = (float*)(sC + 64); // 64
    float* sw2 = sb1 + 64;          // 64

    int tid = threadIdx.x;
    if (tid < 64) { sb1[tid] = b1[tid]; sw2[tid] = W2[tid]; }
    for (int i = tid; i < 2048; i += 256)
        *(float4*)&sB[i * 4] = *(const float4*)&W1[(size_t)i * 4];

    int tx = tid & 15, ty = tid >> 4;
    int c0 = tx * 4, r0 = ty * 4;
    float bb = __ldg(&b2[0]);

    const int NT = ELN / 64;
    for (int tile = blockIdx.x; tile < NT; tile += gridDim.x) {
        int ebase = tile * 64;
        __syncthreads();
        if (tid < 64) sR[tid] = __ldg(&eli[ebase + tid]);
        else if (tid < 128) sC[tid - 64] = __ldg(&eli[ELN + ebase + tid - 64]);
        __syncthreads();
        for (int i = tid; i < 2048; i += 256) {
            int e = i >> 5, sg = i & 31;
            int node = (sg < 16) ? sR[e] : sC[e];
            float4 v = *(const float4*)&z[(size_t)node * 64 + (sg & 15) * 4];
            *(float4*)&sA[e * 132 + sg * 4] = v;
        }
        __syncthreads();

        float4 acc[4];
#pragma unroll
        for (int i = 0; i < 4; i++) acc[i] = make_float4(0.f, 0.f, 0.f, 0.f);

#pragma unroll 4
        for (int k = 0; k < 128; k++) {
            float4 b = *(const float4*)&sB[k * 64 + c0];
#pragma unroll
            for (int i = 0; i < 4; i++) {
                float a = sA[(r0 + i) * 132 + k];
                acc[i].x = fmaf(a, b.x, acc[i].x);
                acc[i].y = fmaf(a, b.y, acc[i].y);
                acc[i].z = fmaf(a, b.z, acc[i].z);
                acc[i].w = fmaf(a, b.w, acc[i].w);
            }
        }

        float p[4];
#pragma unroll
        for (int i = 0; i < 4; i++) {
            float hx = fmaxf(acc[i].x + sb1[c0],     0.f);
            float hy = fmaxf(acc[i].y + sb1[c0 + 1], 0.f);
            float hz = fmaxf(acc[i].z + sb1[c0 + 2], 0.f);
            float hw = fmaxf(acc[i].w + sb1[c0 + 3], 0.f);
            p[i] = hx * sw2[c0] + hy * sw2[c0 + 1] + hz * sw2[c0 + 2] + hw * sw2[c0 + 3];
        }
#pragma unroll
        for (int o = 1; o < 16; o <<= 1) {
#pragma unroll
            for (int i = 0; i < 4; i++) p[i] += __shfl_xor_sync(0xffffffffu, p[i], o);
        }
        if (tx == 0) {
#pragma unroll
            for (int i = 0; i < 4; i++) pred[ebase + r0 + i] = p[i] + bb;
        }
    }
}

// ---------------- launch ----------------
extern "C" void kernel_launch(void* const* d_in, const int* in_sizes, int n_in,
                              void* d_out, int out_size) {
    const float* x     = (const float*)d_in[0];
    const int*   ei    = (const int*)d_in[1];
    const int*   ntype = (const int*)d_in[2];
    const float* eattr = (const float*)d_in[3];
    const int*   etype = (const int*)d_in[4];
    const int*   eli   = (const int*)d_in[5];
    const float* Wx1   = (const float*)d_in[6];
    const float* We1   = (const float*)d_in[7];
    const float* nt1   = (const float*)d_in[8];
    const float* et1   = (const float*)d_in[9];
    const float* as1   = (const float*)d_in[10];
    const float* ad1   = (const float*)d_in[11];
    const float* ae1   = (const float*)d_in[12];
    const float* res1  = (const float*)d_in[13];
    const float* Wx2   = (const float*)d_in[14];
    const float* We2   = (const float*)d_in[15];
    const float* nt2   = (const float*)d_in[16];
    const float* et2   = (const float*)d_in[17];
    const float* as2   = (const float*)d_in[18];
    const float* ad2   = (const float*)d_in[19];
    const float* ae2   = (const float*)d_in[20];
    const float* W1    = (const float*)d_in[21];
    const float* b1    = (const float*)d_in[22];
    const float* W2    = (const float*)d_in[23];
    const float* b2    = (const float*)d_in[24];

    float* pred = (float*)d_out;
    float* zout = pred + ELN;

    size_t smP2 = (size_t)(128 * 68 + 64 * 64 + 512 + 64 + 64 + 128) * sizeof(float);
    size_t smD  = (size_t)(64 * 132 + 128 * 64 + 64 + 64 + 64 + 64) * sizeof(float);
    static bool attr_done = false;
    if (!attr_done) {
        cudaFuncSetAttribute((const void*)k_proj2, cudaFuncAttributeMaxDynamicSharedMemorySize, (int)smP2);
        cudaFuncSetAttribute((const void*)k_dec, cudaFuncAttributeMaxDynamicSharedMemorySize, (int)smD);
        attr_done = true;
    }

    // CSR build
    k_count<<<(EE + 255) / 256, 256>>>(ei);
    k_scanfuse<<<1, 1024>>>(We1, ae1, et1, We2, ae2, et2);
    k_fill<<<(EE + 255) / 256, 256>>>(ei, etype);

    // layer 1 (k_proj1 = 4th launch -> comparable profiled slot)
    k_proj1<<<592, 256>>>(x, ntype, nt1, Wx1, as1, ad1);
    k_score<1><<<(EE + 255) / 256, 256>>>(ei, eattr, etype);
    k_agg1<<<1184, 256>>>(eattr, We1, et1, x, res1);

    // layer 2
    k_proj2<<<dim3((NN + 127) / 128, 4), 256, smP2>>>(ntype, nt2, Wx2, as2, ad2);
    k_score<2><<<(EE + 255) / 256, 256>>>(ei, eattr, etype);
    k_agg2<<<1184, 256>>>(eattr, We2, et2, zout);

    // decoder
    k_dec<<<592, 256, smD>>>(eli, zout, W1, b1, W2, b2, pred);
}

// round 14
// speedup vs baseline: 1.4036x; 1.0464x over previous
#include <cuda_runtime.h>
#include <cuda_fp16.h>
#include <mma.h>
#include <cstdint>

using namespace nvcuda;

#define NN 100000
#define EE 600000
#define ELN 200000

// ---------------- device scratch ----------------
__device__ float  g_h[(size_t)NN * 64];     // layer1 node projections (fp32)
__device__ __half g_h2h[(size_t)NN * 256];  // layer2 node projections (fp16)
__device__ float  g_z1[(size_t)NN * 64];    // layer1 output
__device__ __half g_zh[(size_t)NN * 64];    // fp16 shadow of final z (for decoder gathers)
__device__ float  g_sc[(size_t)EE * 4];     // CSR-ordered scores
__device__ float  g_ss[NN * 4];
__device__ float  g_sd[NN * 4];
__device__ int    g_cnt[NN];
__device__ int    g_rowptr[NN + 1];
__device__ int    g_cur[NN];
__device__ int    g_pos[EE];
__device__ int2   g_meta[EE];               // CSR slot -> (src, etype)
__device__ int    g_eorig[EE];              // CSR slot -> original edge id
__device__ float  g_wae1[64], g_tae1[88];
__device__ float  g_wae2[64], g_tae2[88];

// ---------------- CSR build ----------------
__global__ void k_count(const int* __restrict__ ei) {
    int e = blockIdx.x * blockDim.x + threadIdx.x;
    if (e < EE) atomicAdd(&g_cnt[ei[EE + e]], 1);
}

__global__ void k_scanfuse(const float* __restrict__ We1, const float* __restrict__ ae1,
                           const float* __restrict__ et1,
                           const float* __restrict__ We2, const float* __restrict__ ae2,
                           const float* __restrict__ et2) {
    __shared__ int sp[1024];
    int tid = threadIdx.x;
    if (tid < 64) {
        int k = tid >> 2, h = tid & 3;
        float s = 0.f;
        for (int d = 0; d < 16; d++) s += We1[k * 64 + h * 16 + d] * ae1[h * 16 + d];
        g_wae1[k * 4 + h] = s;
        float s2 = 0.f;
        for (int d = 0; d < 64; d++) s2 += We2[k * 256 + h * 64 + d] * ae2[h * 64 + d];
        g_wae2[k * 4 + h] = s2;
    }
    if (tid < 88) {
        int t = tid >> 2, h = tid & 3;
        float s = 0.f;
        for (int d = 0; d < 16; d++) s += et1[t * 64 + h * 16 + d] * ae1[h * 16 + d];
        g_tae1[t * 4 + h] = s;
        float s2 = 0.f;
        for (int d = 0; d < 64; d++) s2 += et2[t * 256 + h * 64 + d] * ae2[h * 64 + d];
        g_tae2[t * 4 + h] = s2;
    }
    const int chunk = (NN + 1023) >> 10;
    int st = tid * chunk;
    int en = st + chunk; if (en > NN) en = NN;
    int s = 0;
    for (int i = st; i < en; i++) s += g_cnt[i];
    sp[tid] = s;
    __syncthreads();
    for (int o = 1; o < 1024; o <<= 1) {
        int v = (tid >= o) ? sp[tid - o] : 0;
        __syncthreads();
        sp[tid] += v;
        __syncthreads();
    }
    int b = sp[tid] - s;
    for (int i = st; i < en; i++) {
        g_rowptr[i] = b; g_cur[i] = b; b += g_cnt[i];
        g_cnt[i] = 0;   // re-zero for next replay
    }
    if (tid == 1023) g_rowptr[NN] = sp[1023];
}

__global__ void k_fill(const int* __restrict__ ei, const int* __restrict__ etype) {
    int e = blockIdx.x * blockDim.x + threadIdx.x;
    if (e < EE) {
        int d = ei[EE + e];
        int p = atomicAdd(&g_cur[d], 1);
        g_pos[e] = p;
        g_meta[p] = make_int2(ei[e], etype[e]);
        g_eorig[p] = e;
    }
}

// ---------------- layer1 node projection: persistent, Wx in registers ----------------
__global__ void __launch_bounds__(256) k_proj1(const float* __restrict__ x, const int* __restrict__ ntype,
                                               const float* __restrict__ nt, const float* __restrict__ Wx,
                                               const float* __restrict__ a_s, const float* __restrict__ a_d) {
    __shared__ float sNt[8 * 16];
    int tid = threadIdx.x, L = tid & 31, w = tid >> 5;
    for (int i = tid; i < 128; i += 256) sNt[i] = nt[i];

    float W0[16], W1r[16];
#pragma unroll
    for (int k = 0; k < 16; k++) {
        W0[k]  = __ldg(&Wx[k * 64 + L]);
        W1r[k] = __ldg(&Wx[k * 64 + 32 + L]);
    }
    float as0 = __ldg(&a_s[L]), as1 = __ldg(&a_s[32 + L]);
    float ad0 = __ldg(&a_d[L]), ad1 = __ldg(&a_d[32 + L]);
    __syncthreads();

    int nwarps = gridDim.x * 8;
    for (int n = blockIdx.x * 8 + w; n < NN; n += nwarps) {
        int t = __ldg(&ntype[n]);
        float xv = 0.f;
        if (L < 16) xv = __ldg(&x[(size_t)n * 16 + L]) + sNt[t * 16 + L];
        float acc0 = 0.f, acc1 = 0.f;
#pragma unroll
        for (int k = 0; k < 16; k++) {
            float xk = __shfl_sync(0xffffffffu, xv, k);
            acc0 = fmaf(xk, W0[k], acc0);
            acc1 = fmaf(xk, W1r[k], acc1);
        }
        g_h[(size_t)n * 64 + L] = acc0;
        g_h[(size_t)n * 64 + 32 + L] = acc1;

        float pa = acc0 * as0, pb = acc1 * as1;
        float qa = acc0 * ad0, qb = acc1 * ad1;
#pragma unroll
        for (int o = 8; o >= 1; o >>= 1) {
            pa += __shfl_xor_sync(0xffffffffu, pa, o);
            pb += __shfl_xor_sync(0xffffffffu, pb, o);
            qa += __shfl_xor_sync(0xffffffffu, qa, o);
            qb += __shfl_xor_sync(0xffffffffu, qb, o);
        }
        if (L == 0)  { g_ss[n * 4 + 0] = pa; g_ss[n * 4 + 2] = pb; g_sd[n * 4 + 0] = qa; g_sd[n * 4 + 2] = qb; }
        if (L == 16) { g_ss[n * 4 + 1] = pa; g_ss[n * 4 + 3] = pb; g_sd[n * 4 + 1] = qa; g_sd[n * 4 + 3] = qb; }
    }
}

// ---------------- edge scores (raw, post-leaky), scattered to CSR slots ----------------
template <int LAYER>
__global__ void k_score(const int* __restrict__ ei, const float* __restrict__ eattr,
                        const int* __restrict__ etype) {
    __shared__ float sW[64];
    __shared__ float sT[88];
    const float* wae = (LAYER == 1) ? g_wae1 : g_wae2;
    const float* tae = (LAYER == 1) ? g_tae1 : g_tae2;
    if (threadIdx.x < 64) sW[threadIdx.x] = wae[threadIdx.x];
    if (threadIdx.x < 88) sT[threadIdx.x] = tae[threadIdx.x];
    __syncthreads();

    int e = blockIdx.x * blockDim.x + threadIdx.x;
    if (e >= EE) return;
    int s = ei[e], d = ei[EE + e], t = etype[e];
    float sc[4];
#pragma unroll
    for (int h = 0; h < 4; h++)
        sc[h] = g_ss[s * 4 + h] + g_sd[d * 4 + h] + sT[t * 4 + h];

    const float4* ea = (const float4*)(eattr + (size_t)e * 16);
#pragma unroll
    for (int q = 0; q < 4; q++) {
        float4 a = __ldg(ea + q);
#pragma unroll
        for (int h = 0; h < 4; h++) {
            sc[h] = fmaf(a.x, sW[(4 * q + 0) * 4 + h],
                    fmaf(a.y, sW[(4 * q + 1) * 4 + h],
                    fmaf(a.z, sW[(4 * q + 2) * 4 + h],
                    fmaf(a.w, sW[(4 * q + 3) * 4 + h], sc[h]))));
        }
    }
#pragma unroll
    for (int h = 0; h < 4; h++) sc[h] = (sc[h] > 0.f) ? sc[h] : 0.2f * sc[h];
    int p = __ldg(&g_pos[e]);
    *(float4*)&g_sc[(size_t)p * 4] = make_float4(sc[0], sc[1], sc[2], sc[3]);
}

// ---------------- layer1 aggregation: persistent warps, fused softmax, prefetch ----------------
__global__ void __launch_bounds__(256) k_agg1(const float* __restrict__ eattr,
                                              const float* __restrict__ We, const float* __restrict__ et,
                                              const float* __restrict__ x, const float* __restrict__ res) {
    __shared__ float sEt[22 * 64];
    __shared__ float sWe[16 * 64];
    __shared__ float sRes[16 * 64];
    __shared__ float sWs[8 * 64];
    __shared__ float4 sAl[8][32];
    __shared__ int sS[8][32], sTt[8][32], sE[8][32];
    int tid = threadIdx.x, L = tid & 31, w = tid >> 5;
    for (int i = tid; i < 22 * 64; i += 256) sEt[i] = et[i];
    for (int i = tid; i < 16 * 64; i += 256) { sWe[i] = We[i]; sRes[i] = res[i]; }
    __syncthreads();

    const int H = L >> 3, hb = L >> 4;
    for (int n = blockIdx.x * 8 + w; n < NN; n += gridDim.x * 8) {
        int r0 = __ldg(&g_rowptr[n]), r1 = __ldg(&g_rowptr[n + 1]);

        float m[4] = {-3e38f, -3e38f, -3e38f, -3e38f}, dd[4] = {0.f, 0.f, 0.f, 0.f};
        for (int i = r0 + L; i < r1; i += 32) {
            float4 s = *(const float4*)&g_sc[(size_t)i * 4];
            float sv[4] = {s.x, s.y, s.z, s.w};
#pragma unroll
            for (int h = 0; h < 4; h++) {
                if (sv[h] > m[h]) { dd[h] *= __expf(m[h] - sv[h]); m[h] = sv[h]; }
                dd[h] += __expf(sv[h] - m[h]);
            }
        }
#pragma unroll
        for (int o = 16; o >= 1; o >>= 1) {
#pragma unroll
            for (int h = 0; h < 4; h++) {
                float mo = __shfl_xor_sync(0xffffffffu, m[h], o);
                float d_o = __shfl_xor_sync(0xffffffffu, dd[h], o);
                float mn = fmaxf(m[h], mo);
                dd[h] = dd[h] * __expf(m[h] - mn) + d_o * __expf(mo - mn);
                m[h] = mn;
            }
        }
        float inv[4];
#pragma unroll
        for (int h = 0; h < 4; h++) inv[h] = 1.f / (dd[h] + 1e-16f);

        float ax = 0.f, ay = 0.f;
        float w0 = 0.f, w1 = 0.f;
        for (int base = r0; base < r1; base += 32) {
            int nv = min(32, r1 - base);
            if (L < nv) {
                float4 s = *(const float4*)&g_sc[(size_t)(base + L) * 4];
                int2 mt = g_meta[base + L];
                sAl[w][L] = make_float4(__expf(s.x - m[0]) * inv[0], __expf(s.y - m[1]) * inv[1],
                                        __expf(s.z - m[2]) * inv[2], __expf(s.w - m[3]) * inv[3]);
                sS[w][L] = mt.x; sTt[w][L] = mt.y; sE[w][L] = g_eorig[base + L];
            }
            __syncwarp();
            int sj = sS[w][0], tj = sTt[w][0], ej = sE[w][0];
            float2 h2 = *(const float2*)&g_h[(size_t)sj * 64 + 2 * L];
            float ea = __ldg(&eattr[(size_t)ej * 16 + (L & 15)]);
            for (int j = 0; j < nv; j++) {
                float4 al = sAl[w][j];
                float2 ev = *(const float2*)&sEt[tj * 64 + 2 * L];
                float ah = (H == 0) ? al.x : ((H == 1) ? al.y : ((H == 2) ? al.z : al.w));
                ax = fmaf(ah, h2.x + ev.x, ax);
                ay = fmaf(ah, h2.y + ev.y, ay);
                float aw0 = hb ? al.y : al.x, aw1 = hb ? al.w : al.z;
                w0 = fmaf(aw0, ea, w0);
                w1 = fmaf(aw1, ea, w1);
                if (j + 1 < nv) {
                    sj = sS[w][j + 1]; tj = sTt[w][j + 1]; ej = sE[w][j + 1];
                    h2 = *(const float2*)&g_h[(size_t)sj * 64 + 2 * L];
                    ea = __ldg(&eattr[(size_t)ej * 16 + (L & 15)]);
                }
            }
            __syncwarp();
        }
        sWs[w * 64 + L] = w0;
        sWs[w * 64 + 32 + L] = w1;
        __syncwarp();
#pragma unroll
        for (int k = 0; k < 16; k++) {
            float wk = sWs[w * 64 + H * 16 + k];
            float2 we = *(const float2*)&sWe[k * 64 + 2 * L];
            ax = fmaf(wk, we.x, ax);
            ay = fmaf(wk, we.y, ay);
        }
        const float4* xp = (const float4*)(x + (size_t)n * 16);
        float4 xa = __ldg(xp), xb = __ldg(xp + 1), xc = __ldg(xp + 2), xd = __ldg(xp + 3);
        float xv[16] = {xa.x, xa.y, xa.z, xa.w, xb.x, xb.y, xb.z, xb.w,
                        xc.x, xc.y, xc.z, xc.w, xd.x, xd.y, xd.z, xd.w};
#pragma unroll
        for (int k = 0; k < 16; k++) {
            float2 rv = *(const float2*)&sRes[k * 64 + 2 * L];
            ax = fmaf(xv[k], rv.x, ax);
            ay = fmaf(xv[k], rv.y, ay);
        }
        *(float2*)&g_z1[(size_t)n * 64 + 2 * L] = make_float2(fmaxf(ax, 0.f), fmaxf(ay, 0.f));
        __syncwarp();
    }
}

// ---------------- layer2 projection: wmma fp16 GEMM + fused ss/sd, h stored fp16 ----------------
__global__ void __launch_bounds__(256) k_proj2(const int* __restrict__ ntype, const float* __restrict__ nt,
                                               const float* __restrict__ Wx,
                                               const float* __restrict__ a_s, const float* __restrict__ a_d) {
    extern __shared__ char smraw[];
    __half* sA = (__half*)smraw;          // 128 x 80 (ldm 80)
    __half* sB = sA + 128 * 80;           // 64 x 64
    float* sC  = (float*)(sB + 64 * 64);  // 128 x 72
    float* sNt = sC + 128 * 72;           // 512
    float* sAs = sNt + 512;               // 64
    float* sAd = sAs + 64;                // 64
    int*   sTy = (int*)(sAd + 64);        // 128

    int tid = threadIdx.x, L = tid & 31, w = tid >> 5;
    int by = blockIdx.y;
    int rbase = blockIdx.x * 128;

    for (int i = tid; i < 512; i += 256) sNt[i] = nt[i];
    if (tid < 64) { sAs[tid] = a_s[by * 64 + tid]; sAd[tid] = a_d[by * 64 + tid]; }
    if (tid < 128) { int r = rbase + tid; sTy[tid] = (r < NN) ? ntype[r] : 0; }
    for (int i = tid; i < 1024; i += 256) {
        int k = i >> 4, cg = i & 15;
        float4 v = *(const float4*)&Wx[(size_t)k * 256 + by * 64 + cg * 4];
        __half2 a = __floats2half2_rn(v.x, v.y);
        __half2 b = __floats2half2_rn(v.z, v.w);
        uint2 pk; pk.x = *(unsigned*)&a; pk.y = *(unsigned*)&b;
        *(uint2*)&sB[k * 64 + cg * 4] = pk;
    }
    __syncthreads();
    for (int i = tid; i < 2048; i += 256) {
        int r = i >> 4, sg = i & 15;
        int gr = rbase + r;
        float4 v = make_float4(0.f, 0.f, 0.f, 0.f);
        if (gr < NN) {
            v = *(const float4*)&g_z1[(size_t)gr * 64 + sg * 4];
            float4 nv = *(const float4*)&sNt[sTy[r] * 64 + sg * 4];
            v.x += nv.x; v.y += nv.y; v.z += nv.z; v.w += nv.w;
        }
        __half2 a = __floats2half2_rn(v.x, v.y);
        __half2 b = __floats2half2_rn(v.z, v.w);
        uint2 pk; pk.x = *(unsigned*)&a; pk.y = *(unsigned*)&b;
        *(uint2*)&sA[r * 80 + sg * 4] = pk;
    }
    __syncthreads();

    // warp w: rows w*16..w*16+15, all 64 cols
    wmma::fragment<wmma::accumulator, 16, 16, 16, float> fc[4];
#pragma unroll
    for (int c = 0; c < 4; c++) wmma::fill_fragment(fc[c], 0.f);
    for (int k0 = 0; k0 < 64; k0 += 16) {
        wmma::fragment<wmma::matrix_a, 16, 16, 16, __half, wmma::row_major> fa;
        wmma::load_matrix_sync(fa, &sA[w * 16 * 80 + k0], 80);
#pragma unroll
        for (int c = 0; c < 4; c++) {
            wmma::fragment<wmma::matrix_b, 16, 16, 16, __half, wmma::row_major> fb;
            wmma::load_matrix_sync(fb, &sB[k0 * 64 + c * 16], 64);
            wmma::mma_sync(fc[c], fa, fb, fc[c]);
        }
    }
    __syncwarp();
#pragma unroll
    for (int c = 0; c < 4; c++)
        wmma::store_matrix_sync(&sC[w * 16 * 72 + c * 16], fc[c], 72, wmma::mem_row_major);
    __syncwarp();

    // epilogue: write fp16 h + ss/sd dots (fp32)
    for (int r = 0; r < 16; r++) {
        int gr = rbase + w * 16 + r;
        if (gr >= NN) break;
        float h0 = sC[(w * 16 + r) * 72 + L];
        float h1 = sC[(w * 16 + r) * 72 + 32 + L];
        __half2 hp = __floats2half2_rn(h0, h1);
        // store columns L and 32+L as separate halves
        g_h2h[(size_t)gr * 256 + by * 64 + L] = __low2half(hp);
        g_h2h[(size_t)gr * 256 + by * 64 + 32 + L] = __high2half(hp);
        float ps = h0 * sAs[L] + h1 * sAs[32 + L];
        float pd = h0 * sAd[L] + h1 * sAd[32 + L];
#pragma unroll
        for (int o = 16; o >= 1; o >>= 1) {
            ps += __shfl_xor_sync(0xffffffffu, ps, o);
            pd += __shfl_xor_sync(0xffffffffu, pd, o);
        }
        if (L == 0) { g_ss[gr * 4 + by] = ps; g_sd[gr * 4 + by] = pd; }
    }
}

// ---------------- layer2 aggregation: persistent warps, fused softmax, fp16 h gathers ----------------
__global__ void __launch_bounds__(256) k_agg2(const float* __restrict__ eattr,
                                              const float* __restrict__ We, const float* __restrict__ et,
                                              float* __restrict__ zout) {
    __shared__ float4 sEt[22 * 64];
    __shared__ float4 sWe[16 * 64];
    __shared__ float  sWs[8 * 64];
    __shared__ float4 sAl[8][32];
    __shared__ int sS[8][32], sTt[8][32], sE[8][32];
    int tid = threadIdx.x, L = tid & 31, w = tid >> 5;
    for (int i = tid; i < 22 * 64; i += 256) sEt[i] = *(const float4*)&et[(size_t)i * 4];
    for (int i = tid; i < 16 * 64; i += 256) sWe[i] = *(const float4*)&We[(size_t)i * 4];
    __syncthreads();

    const int hb = L >> 4;
    for (int n = blockIdx.x * 8 + w; n < NN; n += gridDim.x * 8) {
        int r0 = __ldg(&g_rowptr[n]), r1 = __ldg(&g_rowptr[n + 1]);

        float m[4] = {-3e38f, -3e38f, -3e38f, -3e38f}, dd[4] = {0.f, 0.f, 0.f, 0.f};
        for (int i = r0 + L; i < r1; i += 32) {
            float4 s = *(const float4*)&g_sc[(size_t)i * 4];
            float sv[4] = {s.x, s.y, s.z, s.w};
#pragma unroll
            for (int h = 0; h < 4; h++) {
                if (sv[h] > m[h]) { dd[h] *= __expf(m[h] - sv[h]); m[h] = sv[h]; }
                dd[h] += __expf(sv[h] - m[h]);
            }
        }
#pragma unroll
        for (int o = 16; o >= 1; o >>= 1) {
#pragma unroll
            for (int h = 0; h < 4; h++) {
                float mo = __shfl_xor_sync(0xffffffffu, m[h], o);
                float d_o = __shfl_xor_sync(0xffffffffu, dd[h], o);
                float mn = fmaxf(m[h], mo);
                dd[h] = dd[h] * __expf(m[h] - mn) + d_o * __expf(mo - mn);
                m[h] = mn;
            }
        }
        float inv[4];
#pragma unroll
        for (int h = 0; h < 4; h++) inv[h] = 1.f / (dd[h] + 1e-16f);

        float4 acc0 = make_float4(0.f, 0.f, 0.f, 0.f);
        float4 acc1 = make_float4(0.f, 0.f, 0.f, 0.f);
        float w0 = 0.f, w1 = 0.f;

        for (int base = r0; base < r1; base += 32) {
            int nv = min(32, r1 - base);
            if (L < nv) {
                float4 s = *(const float4*)&g_sc[(size_t)(base + L) * 4];
                int2 mt = g_meta[base + L];
                sAl[w][L] = make_float4(__expf(s.x - m[0]) * inv[0], __expf(s.y - m[1]) * inv[1],
                                        __expf(s.z - m[2]) * inv[2], __expf(s.w - m[3]) * inv[3]);
                sS[w][L] = mt.x; sTt[w][L] = mt.y; sE[w][L] = g_eorig[base + L];
            }
            __syncwarp();
            int sj = sS[w][0], tj = sTt[w][0], ej = sE[w][0];
            uint2 raw0 = *(const uint2*)&g_h2h[(size_t)sj * 256 + 4 * L];
            uint2 raw1 = *(const uint2*)&g_h2h[(size_t)sj * 256 + 128 + 4 * L];
            float ea = __ldg(&eattr[(size_t)ej * 16 + (L & 15)]);
            for (int j = 0; j < nv; j++) {
                float4 al = sAl[w][j];
                float2 h0a = __half22float2(*(__half2*)&raw0.x);
                float2 h0b = __half22float2(*(__half2*)&raw0.y);
                float2 h1a = __half22float2(*(__half2*)&raw1.x);
                float2 h1b = __half22float2(*(__half2*)&raw1.y);
                float4 e0 = sEt[tj * 64 + L];
                float4 e1 = sEt[tj * 64 + 32 + L];
                float aA = hb ? al.y : al.x;
                float aB = hb ? al.w : al.z;
                acc0.x = fmaf(aA, h0a.x + e0.x, acc0.x);
                acc0.y = fmaf(aA, h0a.y + e0.y, acc0.y);
                acc0.z = fmaf(aA, h0b.x + e0.z, acc0.z);
                acc0.w = fmaf(aA, h0b.y + e0.w, acc0.w);
                acc1.x = fmaf(aB, h1a.x + e1.x, acc1.x);
                acc1.y = fmaf(aB, h1a.y + e1.y, acc1.y);
                acc1.z = fmaf(aB, h1b.x + e1.z, acc1.z);
                acc1.w = fmaf(aB, h1b.y + e1.w, acc1.w);
                w0 = fmaf(aA, ea, w0);
                w1 = fmaf(aB, ea, w1);
                if (j + 1 < nv) {
                    sj = sS[w][j + 1]; tj = sTt[w][j + 1]; ej = sE[w][j + 1];
                    raw0 = *(const uint2*)&g_h2h[(size_t)sj * 256 + 4 * L];
                    raw1 = *(const uint2*)&g_h2h[(size_t)sj * 256 + 128 + 4 * L];
                    ea = __ldg(&eattr[(size_t)ej * 16 + (L & 15)]);
                }
            }
            __syncwarp();
        }
        sWs[w * 64 + L] = w0;
        sWs[w * 64 + 32 + L] = w1;
        __syncwarp();

        const int H0i = hb, H1i = 2 + hb;
#pragma unroll
        for (int k = 0; k < 16; k++) {
            float k0 = sWs[w * 64 + H0i * 16 + k];
            float k1 = sWs[w * 64 + H1i * 16 + k];
            float4 we0 = sWe[k * 64 + L];
            float4 we1 = sWe[k * 64 + 32 + L];
            acc0.x = fmaf(k0, we0.x, acc0.x); acc0.y = fmaf(k0, we0.y, acc0.y);
            acc0.z = fmaf(k0, we0.z, acc0.z); acc0.w = fmaf(k0, we0.w, acc0.w);
            acc1.x = fmaf(k1, we1.x, acc1.x); acc1.y = fmaf(k1, we1.y, acc1.y);
            acc1.z = fmaf(k1, we1.z, acc1.z); acc1.w = fmaf(k1, we1.w, acc1.w);
        }
        float4 sm4;
        sm4.x = acc0.x + acc1.x; sm4.y = acc0.y + acc1.y;
        sm4.z = acc0.z + acc1.z; sm4.w = acc0.w + acc1.w;
        sm4.x += __shfl_xor_sync(0xffffffffu, sm4.x, 16);
        sm4.y += __shfl_xor_sync(0xffffffffu, sm4.y, 16);
        sm4.z += __shfl_xor_sync(0xffffffffu, sm4.z, 16);
        sm4.w += __shfl_xor_sync(0xffffffffu, sm4.w, 16);
        if (L < 16) {
            float4 z1v = *(const float4*)&g_z1[(size_t)n * 64 + 4 * L];
            float4 o;
            o.x = z1v.x + 0.25f * sm4.x;
            o.y = z1v.y + 0.25f * sm4.y;
            o.z = z1v.z + 0.25f * sm4.z;
            o.w = z1v.w + 0.25f * sm4.w;
            *(float4*)&zout[(size_t)n * 64 + 4 * L] = o;
            __half2 za = __floats2half2_rn(o.x, o.y);
            __half2 zb = __floats2half2_rn(o.z, o.w);
            uint2 pk; pk.x = *(unsigned*)&za; pk.y = *(unsigned*)&zb;
            *(uint2*)&g_zh[(size_t)n * 64 + 4 * L] = pk;
        }
        __syncwarp();
    }
}

// ---------------- decoder: persistent wmma fp16 GEMM, fp16 z gathers ----------------
__global__ void __launch_bounds__(256) k_dec(const int* __restrict__ eli,
                                             const float* __restrict__ W1, const float* __restrict__ b1,
                                             const float* __restrict__ W2, const float* __restrict__ b2,
                                             float* __restrict__ pred) {
    extern __shared__ char smraw[];
    __half* sA = (__half*)smraw;            // 64 x 144 (ldm 144)
    __half* sB = sA + 64 * 144;             // 128 x 64
    float* sC  = (float*)(sB + 128 * 64);   // 64 x 72
    int*   sR  = (int*)(sC + 64 * 72);      // 64
    int*   sCn = sR + 64;                   // 64
    float* sb1 = (float*)(sCn + 64);        // 64
    float* sw2 = sb1 + 64;                  // 64

    int tid = threadIdx.x, L = tid & 31, w = tid >> 5;
    if (tid < 64) { sb1[tid] = b1[tid]; sw2[tid] = W2[tid]; }
    for (int i = tid; i < 2048; i += 256) {
        float4 v = *(const float4*)&W1[(size_t)i * 4];
        __half2 a = __floats2half2_rn(v.x, v.y);
        __half2 b = __floats2half2_rn(v.z, v.w);
        uint2 pk; pk.x = *(unsigned*)&a; pk.y = *(unsigned*)&b;
        *(uint2*)&sB[i * 4] = pk;
    }

    float bb = __ldg(&b2[0]);
    const int rt = w >> 1;          // row-tile 0..3 (16 rows each)
    const int ch = w & 1;           // col half (32 cols)

    const int NT = ELN / 64;
    for (int tile = blockIdx.x; tile < NT; tile += gridDim.x) {
        int ebase = tile * 64;
        __syncthreads();
        if (tid < 64) sR[tid] = __ldg(&eli[ebase + tid]);
        else if (tid < 128) sCn[tid - 64] = __ldg(&eli[ELN + ebase + tid - 64]);
        __syncthreads();
        // gather zz rows: 64 edges x 16 segments of 8 halves (16B)
        for (int i = tid; i < 1024; i += 256) {
            int e = i >> 4, sg = i & 15;
            int node = (sg < 8) ? sR[e] : sCn[e];
            uint4 v = *(const uint4*)&g_zh[(size_t)node * 64 + (sg & 7) * 8];
            *(uint4*)&sA[e * 144 + sg * 8] = v;
        }
        __syncthreads();

        wmma::fragment<wmma::accumulator, 16, 16, 16, float> fc[2];
        wmma::fill_fragment(fc[0], 0.f);
        wmma::fill_fragment(fc[1], 0.f);
        for (int k0 = 0; k0 < 128; k0 += 16) {
            wmma::fragment<wmma::matrix_a, 16, 16, 16, __half, wmma::row_major> fa;
            wmma::load_matrix_sync(fa, &sA[rt * 16 * 144 + k0], 144);
#pragma unroll
            for (int cc = 0; cc < 2; cc++) {
                wmma::fragment<wmma::matrix_b, 16, 16, 16, __half, wmma::row_major> fb;
                wmma::load_matrix_sync(fb, &sB[k0 * 64 + (ch * 2 + cc) * 16], 64);
                wmma::mma_sync(fc[cc], fa, fb, fc[cc]);
            }
        }
#pragma unroll
        for (int cc = 0; cc < 2; cc++)
            wmma::store_matrix_sync(&sC[rt * 16 * 72 + (ch * 2 + cc) * 16], fc[cc], 72, wmma::mem_row_major);
        __syncthreads();

        // epilogue: warp w -> edges w*8 .. w*8+7
        for (int r = 0; r < 8; r++) {
            int row = w * 8 + r;
            float hx = fmaxf(sC[row * 72 + L] + sb1[L], 0.f);
            float hy = fmaxf(sC[row * 72 + 32 + L] + sb1[32 + L], 0.f);
            float p = hx * sw2[L] + hy * sw2[32 + L];
#pragma unroll
            for (int o = 16; o >= 1; o >>= 1) p += __shfl_xor_sync(0xffffffffu, p, o);
            if (L == 0) pred[ebase + row] = p + bb;
        }
    }
}

// ---------------- launch ----------------
extern "C" void kernel_launch(void* const* d_in, const int* in_sizes, int n_in,
                              void* d_out, int out_size) {
    const float* x     = (const float*)d_in[0];
    const int*   ei    = (const int*)d_in[1];
    const int*   ntype = (const int*)d_in[2];
    const float* eattr = (const float*)d_in[3];
    const int*   etype = (const int*)d_in[4];
    const int*   eli   = (const int*)d_in[5];
    const float* Wx1   = (const float*)d_in[6];
    const float* We1   = (const float*)d_in[7];
    const float* nt1   = (const float*)d_in[8];
    const float* et1   = (const float*)d_in[9];
    const float* as1   = (const float*)d_in[10];
    const float* ad1   = (const float*)d_in[11];
    const float* ae1   = (const float*)d_in[12];
    const float* res1  = (const float*)d_in[13];
    const float* Wx2   = (const float*)d_in[14];
    const float* We2   = (const float*)d_in[15];
    const float* nt2   = (const float*)d_in[16];
    const float* et2   = (const float*)d_in[17];
    const float* as2   = (const float*)d_in[18];
    const float* ad2   = (const float*)d_in[19];
    const float* ae2   = (const float*)d_in[20];
    const float* W1    = (const float*)d_in[21];
    const float* b1    = (const float*)d_in[22];
    const float* W2    = (const float*)d_in[23];
    const float* b2    = (const float*)d_in[24];

    float* pred = (float*)d_out;
    float* zout = pred + ELN;

    size_t smP2 = 128 * 80 * 2 + 64 * 64 * 2 + 128 * 72 * 4 + 512 * 4 + 64 * 4 + 64 * 4 + 128 * 4;
    size_t smD  = 64 * 144 * 2 + 128 * 64 * 2 + 64 * 72 * 4 + 64 * 4 + 64 * 4 + 64 * 4 + 64 * 4;
    static bool attr_done = false;
    if (!attr_done) {
        cudaFuncSetAttribute((const void*)k_proj2, cudaFuncAttributeMaxDynamicSharedMemorySize, (int)smP2);
        cudaFuncSetAttribute((const void*)k_dec, cudaFuncAttributeMaxDynamicSharedMemorySize, (int)smD);
        attr_done = true;
    }

    // CSR build
    k_count<<<(EE + 255) / 256, 256>>>(ei);
    k_scanfuse<<<1, 1024>>>(We1, ae1, et1, We2, ae2, et2);
    k_fill<<<(EE + 255) / 256, 256>>>(ei, etype);

    // layer 1 (k_proj1 = 4th launch -> comparable profiled slot)
    k_proj1<<<592, 256>>>(x, ntype, nt1, Wx1, as1, ad1);
    k_score<1><<<(EE + 255) / 256, 256>>>(ei, eattr, etype);
    k_agg1<<<1184, 256>>>(eattr, We1, et1, x, res1);

    // layer 2
    k_proj2<<<dim3((NN + 127) / 128, 4), 256, smP2>>>(ntype, nt2, Wx2, as2, ad2);
    k_score<2><<<(EE + 255) / 256, 256>>>(ei, eattr, etype);
    k_agg2<<<1184, 256>>>(eattr, We2, et2, zout);

    // decoder
    k_dec<<<592, 256, smD>>>(eli, W1, b1, W2, b2, pred);
}

// round 15
// speedup vs baseline: 1.4060x; 1.0017x over previous
#include <cuda_runtime.h>
#include <cuda_fp16.h>
#include <mma.h>
#include <cstdint>

using namespace nvcuda;

#define NN 100000
#define EE 600000
#define ELN 200000

// ---------------- device scratch ----------------
__device__ __half g_hh[(size_t)NN * 64];    // layer1 node projections (fp16, col-pair layout)
__device__ __half g_h2h[(size_t)NN * 256];  // layer2 node projections (fp16)
__device__ float  g_z1[(size_t)NN * 64];    // layer1 output
__device__ __half g_zh[(size_t)NN * 64];    // fp16 shadow of final z (decoder gathers)
__device__ float  g_sc[(size_t)EE * 4];     // CSR-ordered scores
__device__ float  g_ss[NN * 4];
__device__ float  g_sd[NN * 4];
__device__ int    g_cnt[NN];
__device__ int    g_rowptr[NN + 1];
__device__ int    g_cur[NN];
__device__ int    g_pos[EE];
__device__ int4   g_mt[EE];                 // CSR slot -> (src, etype, orig, 0)
__device__ float  g_wae1[64], g_tae1[88];
__device__ float  g_wae2[64], g_tae2[88];

// ---------------- CSR build ----------------
__global__ void k_count(const int* __restrict__ ei) {
    int e = blockIdx.x * blockDim.x + threadIdx.x;
    if (e < EE) atomicAdd(&g_cnt[ei[EE + e]], 1);
}

__global__ void k_scanfuse(const float* __restrict__ We1, const float* __restrict__ ae1,
                           const float* __restrict__ et1,
                           const float* __restrict__ We2, const float* __restrict__ ae2,
                           const float* __restrict__ et2) {
    __shared__ int sp[1024];
    int tid = threadIdx.x;
    if (tid < 64) {
        int k = tid >> 2, h = tid & 3;
        float s = 0.f;
        for (int d = 0; d < 16; d++) s += We1[k * 64 + h * 16 + d] * ae1[h * 16 + d];
        g_wae1[k * 4 + h] = s;
        float s2 = 0.f;
        for (int d = 0; d < 64; d++) s2 += We2[k * 256 + h * 64 + d] * ae2[h * 64 + d];
        g_wae2[k * 4 + h] = s2;
    }
    if (tid < 88) {
        int t = tid >> 2, h = tid & 3;
        float s = 0.f;
        for (int d = 0; d < 16; d++) s += et1[t * 64 + h * 16 + d] * ae1[h * 16 + d];
        g_tae1[t * 4 + h] = s;
        float s2 = 0.f;
        for (int d = 0; d < 64; d++) s2 += et2[t * 256 + h * 64 + d] * ae2[h * 64 + d];
        g_tae2[t * 4 + h] = s2;
    }
    const int chunk = (NN + 1023) >> 10;
    int st = tid * chunk;
    int en = st + chunk; if (en > NN) en = NN;
    int s = 0;
    for (int i = st; i < en; i++) s += g_cnt[i];
    sp[tid] = s;
    __syncthreads();
    for (int o = 1; o < 1024; o <<= 1) {
        int v = (tid >= o) ? sp[tid - o] : 0;
        __syncthreads();
        sp[tid] += v;
        __syncthreads();
    }
    int b = sp[tid] - s;
    for (int i = st; i < en; i++) {
        g_rowptr[i] = b; g_cur[i] = b; b += g_cnt[i];
        g_cnt[i] = 0;   // re-zero for next replay
    }
    if (tid == 1023) g_rowptr[NN] = sp[1023];
}

__global__ void k_fill(const int* __restrict__ ei, const int* __restrict__ etype) {
    int e = blockIdx.x * blockDim.x + threadIdx.x;
    if (e < EE) {
        int d = ei[EE + e];
        int p = atomicAdd(&g_cur[d], 1);
        g_pos[e] = p;
        g_mt[p] = make_int4(ei[e], etype[e], e, 0);
    }
}

// ---------------- layer1 node projection: persistent, Wx in registers, fp16 out ----------------
// lane L owns columns 2L, 2L+1 (same head h = L>>3)
__global__ void __launch_bounds__(256) k_proj1(const float* __restrict__ x, const int* __restrict__ ntype,
                                               const float* __restrict__ nt, const float* __restrict__ Wx,
                                               const float* __restrict__ a_s, const float* __restrict__ a_d) {
    __shared__ float sNt[8 * 16];
    int tid = threadIdx.x, L = tid & 31, w = tid >> 5;
    for (int i = tid; i < 128; i += 256) sNt[i] = nt[i];

    float W0[16], W1r[16];
#pragma unroll
    for (int k = 0; k < 16; k++) {
        W0[k]  = __ldg(&Wx[k * 64 + 2 * L]);
        W1r[k] = __ldg(&Wx[k * 64 + 2 * L + 1]);
    }
    float as0 = __ldg(&a_s[2 * L]), as1 = __ldg(&a_s[2 * L + 1]);
    float ad0 = __ldg(&a_d[2 * L]), ad1 = __ldg(&a_d[2 * L + 1]);
    __syncthreads();

    const int H = L >> 3;
    int nwarps = gridDim.x * 8;
    for (int n = blockIdx.x * 8 + w; n < NN; n += nwarps) {
        int t = __ldg(&ntype[n]);
        float xv = 0.f;
        if (L < 16) xv = __ldg(&x[(size_t)n * 16 + L]) + sNt[t * 16 + L];
        float acc0 = 0.f, acc1 = 0.f;
#pragma unroll
        for (int k = 0; k < 16; k++) {
            float xk = __shfl_sync(0xffffffffu, xv, k);
            acc0 = fmaf(xk, W0[k], acc0);
            acc1 = fmaf(xk, W1r[k], acc1);
        }
        *(__half2*)&g_hh[(size_t)n * 64 + 2 * L] = __floats2half2_rn(acc0, acc1);

        float pa = acc0 * as0 + acc1 * as1;
        float qa = acc0 * ad0 + acc1 * ad1;
#pragma unroll
        for (int o = 4; o >= 1; o >>= 1) {
            pa += __shfl_xor_sync(0xffffffffu, pa, o);
            qa += __shfl_xor_sync(0xffffffffu, qa, o);
        }
        if ((L & 7) == 0) {
            g_ss[n * 4 + H] = pa;
            g_sd[n * 4 + H] = qa;
        }
    }
}

// ---------------- edge scores (raw, post-leaky), scattered to CSR slots ----------------
template <int LAYER>
__global__ void k_score(const int* __restrict__ ei, const float* __restrict__ eattr,
                        const int* __restrict__ etype) {
    __shared__ float sW[64];
    __shared__ float sT[88];
    const float* wae = (LAYER == 1) ? g_wae1 : g_wae2;
    const float* tae = (LAYER == 1) ? g_tae1 : g_tae2;
    if (threadIdx.x < 64) sW[threadIdx.x] = wae[threadIdx.x];
    if (threadIdx.x < 88) sT[threadIdx.x] = tae[threadIdx.x];
    __syncthreads();

    int e = blockIdx.x * blockDim.x + threadIdx.x;
    if (e >= EE) return;
    int s = ei[e], d = ei[EE + e], t = etype[e];
    float sc[4];
#pragma unroll
    for (int h = 0; h < 4; h++)
        sc[h] = g_ss[s * 4 + h] + g_sd[d * 4 + h] + sT[t * 4 + h];

    const float4* ea = (const float4*)(eattr + (size_t)e * 16);
#pragma unroll
    for (int q = 0; q < 4; q++) {
        float4 a = __ldg(ea + q);
#pragma unroll
        for (int h = 0; h < 4; h++) {
            sc[h] = fmaf(a.x, sW[(4 * q + 0) * 4 + h],
                    fmaf(a.y, sW[(4 * q + 1) * 4 + h],
                    fmaf(a.z, sW[(4 * q + 2) * 4 + h],
                    fmaf(a.w, sW[(4 * q + 3) * 4 + h], sc[h]))));
        }
    }
#pragma unroll
    for (int h = 0; h < 4; h++) sc[h] = (sc[h] > 0.f) ? sc[h] : 0.2f * sc[h];
    int p = __ldg(&g_pos[e]);
    *(float4*)&g_sc[(size_t)p * 4] = make_float4(sc[0], sc[1], sc[2], sc[3]);
}

// ---------------- layer1 aggregation: persistent warps, fused softmax, fp16 h gathers ----------------
__global__ void __launch_bounds__(256) k_agg1(const float* __restrict__ eattr,
                                              const float* __restrict__ We, const float* __restrict__ et,
                                              const float* __restrict__ x, const float* __restrict__ res) {
    __shared__ float sEt[22 * 64];
    __shared__ float sWe[16 * 64];
    __shared__ float sRes[16 * 64];
    __shared__ float sWs[8 * 64];
    __shared__ float4 sAl[8][32];
    __shared__ int sS[8][32], sTt[8][32], sE[8][32];
    int tid = threadIdx.x, L = tid & 31, w = tid >> 5;
    for (int i = tid; i < 22 * 64; i += 256) sEt[i] = et[i];
    for (int i = tid; i < 16 * 64; i += 256) { sWe[i] = We[i]; sRes[i] = res[i]; }
    __syncthreads();

    const int H = L >> 3, hb = L >> 4;
    for (int n = blockIdx.x * 8 + w; n < NN; n += gridDim.x * 8) {
        int r0 = __ldg(&g_rowptr[n]), r1 = __ldg(&g_rowptr[n + 1]);

        float m[4] = {-3e38f, -3e38f, -3e38f, -3e38f}, dd[4] = {0.f, 0.f, 0.f, 0.f};
        for (int i = r0 + L; i < r1; i += 32) {
            float4 s = *(const float4*)&g_sc[(size_t)i * 4];
            float sv[4] = {s.x, s.y, s.z, s.w};
#pragma unroll
            for (int h = 0; h < 4; h++) {
                if (sv[h] > m[h]) { dd[h] *= __expf(m[h] - sv[h]); m[h] = sv[h]; }
                dd[h] += __expf(sv[h] - m[h]);
            }
        }
#pragma unroll
        for (int o = 16; o >= 1; o >>= 1) {
#pragma unroll
            for (int h = 0; h < 4; h++) {
                float mo = __shfl_xor_sync(0xffffffffu, m[h], o);
                float d_o = __shfl_xor_sync(0xffffffffu, dd[h], o);
                float mn = fmaxf(m[h], mo);
                dd[h] = dd[h] * __expf(m[h] - mn) + d_o * __expf(mo - mn);
                m[h] = mn;
            }
        }
        float inv[4];
#pragma unroll
        for (int h = 0; h < 4; h++) inv[h] = 1.f / (dd[h] + 1e-16f);

        float ax = 0.f, ay = 0.f;
        float w0 = 0.f, w1 = 0.f;
        for (int base = r0; base < r1; base += 32) {
            int nv = min(32, r1 - base);
            if (L < nv) {
                float4 s = *(const float4*)&g_sc[(size_t)(base + L) * 4];
                int4 mt = g_mt[base + L];
                sAl[w][L] = make_float4(__expf(s.x - m[0]) * inv[0], __expf(s.y - m[1]) * inv[1],
                                        __expf(s.z - m[2]) * inv[2], __expf(s.w - m[3]) * inv[3]);
                sS[w][L] = mt.x; sTt[w][L] = mt.y; sE[w][L] = mt.z;
            }
            __syncwarp();
            int sj = sS[w][0], tj = sTt[w][0], ej = sE[w][0];
            __half2 hr = *(const __half2*)&g_hh[(size_t)sj * 64 + 2 * L];
            float ea = __ldg(&eattr[(size_t)ej * 16 + (L & 15)]);
            for (int j = 0; j < nv; j++) {
                float4 al = sAl[w][j];
                float2 h2 = __half22float2(hr);
                float2 ev = *(const float2*)&sEt[tj * 64 + 2 * L];
                float ah = (H == 0) ? al.x : ((H == 1) ? al.y : ((H == 2) ? al.z : al.w));
                ax = fmaf(ah, h2.x + ev.x, ax);
                ay = fmaf(ah, h2.y + ev.y, ay);
                float aw0 = hb ? al.y : al.x, aw1 = hb ? al.w : al.z;
                w0 = fmaf(aw0, ea, w0);
                w1 = fmaf(aw1, ea, w1);
                if (j + 1 < nv) {
                    sj = sS[w][j + 1]; tj = sTt[w][j + 1]; ej = sE[w][j + 1];
                    hr = *(const __half2*)&g_hh[(size_t)sj * 64 + 2 * L];
                    ea = __ldg(&eattr[(size_t)ej * 16 + (L & 15)]);
                }
            }
            __syncwarp();
        }
        sWs[w * 64 + L] = w0;
        sWs[w * 64 + 32 + L] = w1;
        __syncwarp();
#pragma unroll
        for (int k = 0; k < 16; k++) {
            float wk = sWs[w * 64 + H * 16 + k];
            float2 we = *(const float2*)&sWe[k * 64 + 2 * L];
            ax = fmaf(wk, we.x, ax);
            ay = fmaf(wk, we.y, ay);
        }
        const float4* xp = (const float4*)(x + (size_t)n * 16);
        float4 xa = __ldg(xp), xb = __ldg(xp + 1), xc = __ldg(xp + 2), xd = __ldg(xp + 3);
        float xv[16] = {xa.x, xa.y, xa.z, xa.w, xb.x, xb.y, xb.z, xb.w,
                        xc.x, xc.y, xc.z, xc.w, xd.x, xd.y, xd.z, xd.w};
#pragma unroll
        for (int k = 0; k < 16; k++) {
            float2 rv = *(const float2*)&sRes[k * 64 + 2 * L];
            ax = fmaf(xv[k], rv.x, ax);
            ay = fmaf(xv[k], rv.y, ay);
        }
        *(float2*)&g_z1[(size_t)n * 64 + 2 * L] = make_float2(fmaxf(ax, 0.f), fmaxf(ay, 0.f));
        __syncwarp();
    }
}

// ---------------- layer2 projection: wmma fp16 GEMM + fused ss/sd, h stored fp16 ----------------
__global__ void __launch_bounds__(256) k_proj2(const int* __restrict__ ntype, const float* __restrict__ nt,
                                               const float* __restrict__ Wx,
                                               const float* __restrict__ a_s, const float* __restrict__ a_d) {
    extern __shared__ char smraw[];
    __half* sA = (__half*)smraw;          // 128 x 80
    __half* sB = sA + 128 * 80;           // 64 x 64
    float* sC  = (float*)(sB + 64 * 64);  // 128 x 72
    float* sNt = sC + 128 * 72;           // 512
    float* sAs = sNt + 512;               // 64
    float* sAd = sAs + 64;                // 64
    int*   sTy = (int*)(sAd + 64);        // 128

    int tid = threadIdx.x, L = tid & 31, w = tid >> 5;
    int by = blockIdx.y;
    int rbase = blockIdx.x * 128;

    for (int i = tid; i < 512; i += 256) sNt[i] = nt[i];
    if (tid < 64) { sAs[tid] = a_s[by * 64 + tid]; sAd[tid] = a_d[by * 64 + tid]; }
    if (tid < 128) { int r = rbase + tid; sTy[tid] = (r < NN) ? ntype[r] : 0; }
    for (int i = tid; i < 1024; i += 256) {
        int k = i >> 4, cg = i & 15;
        float4 v = *(const float4*)&Wx[(size_t)k * 256 + by * 64 + cg * 4];
        __half2 a = __floats2half2_rn(v.x, v.y);
        __half2 b = __floats2half2_rn(v.z, v.w);
        uint2 pk; pk.x = *(unsigned*)&a; pk.y = *(unsigned*)&b;
        *(uint2*)&sB[k * 64 + cg * 4] = pk;
    }
    __syncthreads();
    for (int i = tid; i < 2048; i += 256) {
        int r = i >> 4, sg = i & 15;
        int gr = rbase + r;
        float4 v = make_float4(0.f, 0.f, 0.f, 0.f);
        if (gr < NN) {
            v = *(const float4*)&g_z1[(size_t)gr * 64 + sg * 4];
            float4 nv = *(const float4*)&sNt[sTy[r] * 64 + sg * 4];
            v.x += nv.x; v.y += nv.y; v.z += nv.z; v.w += nv.w;
        }
        __half2 a = __floats2half2_rn(v.x, v.y);
        __half2 b = __floats2half2_rn(v.z, v.w);
        uint2 pk; pk.x = *(unsigned*)&a; pk.y = *(unsigned*)&b;
        *(uint2*)&sA[r * 80 + sg * 4] = pk;
    }
    __syncthreads();

    wmma::fragment<wmma::accumulator, 16, 16, 16, float> fc[4];
#pragma unroll
    for (int c = 0; c < 4; c++) wmma::fill_fragment(fc[c], 0.f);
    for (int k0 = 0; k0 < 64; k0 += 16) {
        wmma::fragment<wmma::matrix_a, 16, 16, 16, __half, wmma::row_major> fa;
        wmma::load_matrix_sync(fa, &sA[w * 16 * 80 + k0], 80);
#pragma unroll
        for (int c = 0; c < 4; c++) {
            wmma::fragment<wmma::matrix_b, 16, 16, 16, __half, wmma::row_major> fb;
            wmma::load_matrix_sync(fb, &sB[k0 * 64 + c * 16], 64);
            wmma::mma_sync(fc[c], fa, fb, fc[c]);
        }
    }
    __syncwarp();
#pragma unroll
    for (int c = 0; c < 4; c++)
        wmma::store_matrix_sync(&sC[w * 16 * 72 + c * 16], fc[c], 72, wmma::mem_row_major);
    __syncwarp();

    for (int r = 0; r < 16; r++) {
        int gr = rbase + w * 16 + r;
        if (gr >= NN) break;
        float h0 = sC[(w * 16 + r) * 72 + L];
        float h1 = sC[(w * 16 + r) * 72 + 32 + L];
        __half2 hp = __floats2half2_rn(h0, h1);
        g_h2h[(size_t)gr * 256 + by * 64 + L] = __low2half(hp);
        g_h2h[(size_t)gr * 256 + by * 64 + 32 + L] = __high2half(hp);
        float ps = h0 * sAs[L] + h1 * sAs[32 + L];
        float pd = h0 * sAd[L] + h1 * sAd[32 + L];
#pragma unroll
        for (int o = 16; o >= 1; o >>= 1) {
            ps += __shfl_xor_sync(0xffffffffu, ps, o);
            pd += __shfl_xor_sync(0xffffffffu, pd, o);
        }
        if (L == 0) { g_ss[gr * 4 + by] = ps; g_sd[gr * 4 + by] = pd; }
    }
}

// ---------------- layer2 aggregation: persistent warps, fused softmax, fp16 h gathers ----------------
__global__ void __launch_bounds__(256) k_agg2(const float* __restrict__ eattr,
                                              const float* __restrict__ We, const float* __restrict__ et,
                                              float* __restrict__ zout) {
    __shared__ float4 sEt[22 * 64];
    __shared__ float4 sWe[16 * 64];
    __shared__ float  sWs[8 * 64];
    __shared__ float4 sAl[8][32];
    __shared__ int sS[8][32], sTt[8][32], sE[8][32];
    int tid = threadIdx.x, L = tid & 31, w = tid >> 5;
    for (int i = tid; i < 22 * 64; i += 256) sEt[i] = *(const float4*)&et[(size_t)i * 4];
    for (int i = tid; i < 16 * 64; i += 256) sWe[i] = *(const float4*)&We[(size_t)i * 4];
    __syncthreads();

    const int hb = L >> 4;
    for (int n = blockIdx.x * 8 + w; n < NN; n += gridDim.x * 8) {
        int r0 = __ldg(&g_rowptr[n]), r1 = __ldg(&g_rowptr[n + 1]);

        float m[4] = {-3e38f, -3e38f, -3e38f, -3e38f}, dd[4] = {0.f, 0.f, 0.f, 0.f};
        for (int i = r0 + L; i < r1; i += 32) {
            float4 s = *(const float4*)&g_sc[(size_t)i * 4];
            float sv[4] = {s.x, s.y, s.z, s.w};
#pragma unroll
            for (int h = 0; h < 4; h++) {
                if (sv[h] > m[h]) { dd[h] *= __expf(m[h] - sv[h]); m[h] = sv[h]; }
                dd[h] += __expf(sv[h] - m[h]);
            }
        }
#pragma unroll
        for (int o = 16; o >= 1; o >>= 1) {
#pragma unroll
            for (int h = 0; h < 4; h++) {
                float mo = __shfl_xor_sync(0xffffffffu, m[h], o);
                float d_o = __shfl_xor_sync(0xffffffffu, dd[h], o);
                float mn = fmaxf(m[h], mo);
                dd[h] = dd[h] * __expf(m[h] - mn) + d_o * __expf(mo - mn);
                m[h] = mn;
            }
        }
        float inv[4];
#pragma unroll
        for (int h = 0; h < 4; h++) inv[h] = 1.f / (dd[h] + 1e-16f);

        float4 acc0 = make_float4(0.f, 0.f, 0.f, 0.f);
        float4 acc1 = make_float4(0.f, 0.f, 0.f, 0.f);
        float w0 = 0.f, w1 = 0.f;

        for (int base = r0; base < r1; base += 32) {
            int nv = min(32, r1 - base);
            if (L < nv) {
                float4 s = *(const float4*)&g_sc[(size_t)(base + L) * 4];
                int4 mt = g_mt[base + L];
                sAl[w][L] = make_float4(__expf(s.x - m[0]) * inv[0], __expf(s.y - m[1]) * inv[1],
                                        __expf(s.z - m[2]) * inv[2], __expf(s.w - m[3]) * inv[3]);
                sS[w][L] = mt.x; sTt[w][L] = mt.y; sE[w][L] = mt.z;
            }
            __syncwarp();
            int sj = sS[w][0], tj = sTt[w][0], ej = sE[w][0];
            uint2 raw0 = *(const uint2*)&g_h2h[(size_t)sj * 256 + 4 * L];
            uint2 raw1 = *(const uint2*)&g_h2h[(size_t)sj * 256 + 128 + 4 * L];
            float ea = __ldg(&eattr[(size_t)ej * 16 + (L & 15)]);
            for (int j = 0; j < nv; j++) {
                float4 al = sAl[w][j];
                float2 h0a = __half22float2(*(__half2*)&raw0.x);
                float2 h0b = __half22float2(*(__half2*)&raw0.y);
                float2 h1a = __half22float2(*(__half2*)&raw1.x);
                float2 h1b = __half22float2(*(__half2*)&raw1.y);
                float4 e0 = sEt[tj * 64 + L];
                float4 e1 = sEt[tj * 64 + 32 + L];
                float aA = hb ? al.y : al.x;
                float aB = hb ? al.w : al.z;
                acc0.x = fmaf(aA, h0a.x + e0.x, acc0.x);
                acc0.y = fmaf(aA, h0a.y + e0.y, acc0.y);
                acc0.z = fmaf(aA, h0b.x + e0.z, acc0.z);
                acc0.w = fmaf(aA, h0b.y + e0.w, acc0.w);
                acc1.x = fmaf(aB, h1a.x + e1.x, acc1.x);
                acc1.y = fmaf(aB, h1a.y + e1.y, acc1.y);
                acc1.z = fmaf(aB, h1b.x + e1.z, acc1.z);
                acc1.w = fmaf(aB, h1b.y + e1.w, acc1.w);
                w0 = fmaf(aA, ea, w0);
                w1 = fmaf(aB, ea, w1);
                if (j + 1 < nv) {
                    sj = sS[w][j + 1]; tj = sTt[w][j + 1]; ej = sE[w][j + 1];
                    raw0 = *(const uint2*)&g_h2h[(size_t)sj * 256 + 4 * L];
                    raw1 = *(const uint2*)&g_h2h[(size_t)sj * 256 + 128 + 4 * L];
                    ea = __ldg(&eattr[(size_t)ej * 16 + (L & 15)]);
                }
            }
            __syncwarp();
        }
        sWs[w * 64 + L] = w0;
        sWs[w * 64 + 32 + L] = w1;
        __syncwarp();

        const int H0i = hb, H1i = 2 + hb;
#pragma unroll
        for (int k = 0; k < 16; k++) {
            float k0 = sWs[w * 64 + H0i * 16 + k];
            float k1 = sWs[w * 64 + H1i * 16 + k];
            float4 we0 = sWe[k * 64 + L];
            float4 we1 = sWe[k * 64 + 32 + L];
            acc0.x = fmaf(k0, we0.x, acc0.x); acc0.y = fmaf(k0, we0.y, acc0.y);
            acc0.z = fmaf(k0, we0.z, acc0.z); acc0.w = fmaf(k0, we0.w, acc0.w);
            acc1.x = fmaf(k1, we1.x, acc1.x); acc1.y = fmaf(k1, we1.y, acc1.y);
            acc1.z = fmaf(k1, we1.z, acc1.z); acc1.w = fmaf(k1, we1.w, acc1.w);
        }
        float4 sm4;
        sm4.x = acc0.x + acc1.x; sm4.y = acc0.y + acc1.y;
        sm4.z = acc0.z + acc1.z; sm4.w = acc0.w + acc1.w;
        sm4.x += __shfl_xor_sync(0xffffffffu, sm4.x, 16);
        sm4.y += __shfl_xor_sync(0xffffffffu, sm4.y, 16);
        sm4.z += __shfl_xor_sync(0xffffffffu, sm4.z, 16);
        sm4.w += __shfl_xor_sync(0xffffffffu, sm4.w, 16);
        if (L < 16) {
            float4 z1v = *(const float4*)&g_z1[(size_t)n * 64 + 4 * L];
            float4 o;
            o.x = z1v.x + 0.25f * sm4.x;
            o.y = z1v.y + 0.25f * sm4.y;
            o.z = z1v.z + 0.25f * sm4.z;
            o.w = z1v.w + 0.25f * sm4.w;
            *(float4*)&zout[(size_t)n * 64 + 4 * L] = o;
            __half2 za = __floats2half2_rn(o.x, o.y);
            __half2 zb = __floats2half2_rn(o.z, o.w);
            uint2 pk; pk.x = *(unsigned*)&za; pk.y = *(unsigned*)&zb;
            *(uint2*)&g_zh[(size_t)n * 64 + 4 * L] = pk;
        }
        __syncwarp();
    }
}

// ---------------- decoder: persistent wmma fp16 GEMM, fp16 z gathers ----------------
__global__ void __launch_bounds__(256) k_dec(const int* __restrict__ eli,
                                             const float* __restrict__ W1, const float* __restrict__ b1,
                                             const float* __restrict__ W2, const float* __restrict__ b2,
                                             float* __restrict__ pred) {
    extern __shared__ char smraw[];
    __half* sA = (__half*)smraw;            // 64 x 144
    __half* sB = sA + 64 * 144;             // 128 x 64
    float* sC  = (float*)(sB + 128 * 64);   // 64 x 72
    int*   sR  = (int*)(sC + 64 * 72);      // 64
    int*   sCn = sR + 64;                   // 64
    float* sb1 = (float*)(sCn + 64);        // 64
    float* sw2 = sb1 + 64;                  // 64

    int tid = threadIdx.x, L = tid & 31, w = tid >> 5;
    if (tid < 64) { sb1[tid] = b1[tid]; sw2[tid] = W2[tid]; }
    for (int i = tid; i < 2048; i += 256) {
        float4 v = *(const float4*)&W1[(size_t)i * 4];
        __half2 a = __floats2half2_rn(v.x, v.y);
        __half2 b = __floats2half2_rn(v.z, v.w);
        uint2 pk; pk.x = *(unsigned*)&a; pk.y = *(unsigned*)&b;
        *(uint2*)&sB[i * 4] = pk;
    }

    float bb = __ldg(&b2[0]);
    const int rt = w >> 1;
    const int ch = w & 1;

    const int NT = ELN / 64;
    for (int tile = blockIdx.x; tile < NT; tile += gridDim.x) {
        int ebase = tile * 64;
        __syncthreads();
        if (tid < 64) sR[tid] = __ldg(&eli[ebase + tid]);
        else if (tid < 128) sCn[tid - 64] = __ldg(&eli[ELN + ebase + tid - 64]);
        __syncthreads();
        for (int i = tid; i < 1024; i += 256) {
            int e = i >> 4, sg = i & 15;
            int node = (sg < 8) ? sR[e] : sCn[e];
            uint4 v = *(const uint4*)&g_zh[(size_t)node * 64 + (sg & 7) * 8];
            *(uint4*)&sA[e * 144 + sg * 8] = v;
        }
        __syncthreads();

        wmma::fragment<wmma::accumulator, 16, 16, 16, float> fc[2];
        wmma::fill_fragment(fc[0], 0.f);
        wmma::fill_fragment(fc[1], 0.f);
        for (int k0 = 0; k0 < 128; k0 += 16) {
            wmma::fragment<wmma::matrix_a, 16, 16, 16, __half, wmma::row_major> fa;
            wmma::load_matrix_sync(fa, &sA[rt * 16 * 144 + k0], 144);
#pragma unroll
            for (int cc = 0; cc < 2; cc++) {
                wmma::fragment<wmma::matrix_b, 16, 16, 16, __half, wmma::row_major> fb;
                wmma::load_matrix_sync(fb, &sB[k0 * 64 + (ch * 2 + cc) * 16], 64);
                wmma::mma_sync(fc[cc], fa, fb, fc[cc]);
            }
        }
#pragma unroll
        for (int cc = 0; cc < 2; cc++)
            wmma::store_matrix_sync(&sC[rt * 16 * 72 + (ch * 2 + cc) * 16], fc[cc], 72, wmma::mem_row_major);
        __syncthreads();

        for (int r = 0; r < 8; r++) {
            int row = w * 8 + r;
            float hx = fmaxf(sC[row * 72 + L] + sb1[L], 0.f);
            float hy = fmaxf(sC[row * 72 + 32 + L] + sb1[32 + L], 0.f);
            float p = hx * sw2[L] + hy * sw2[32 + L];
#pragma unroll
            for (int o = 16; o >= 1; o >>= 1) p += __shfl_xor_sync(0xffffffffu, p, o);
            if (L == 0) pred[ebase + row] = p + bb;
        }
    }
}

// ---------------- launch ----------------
extern "C" void kernel_launch(void* const* d_in, const int* in_sizes, int n_in,
                              void* d_out, int out_size) {
    const float* x     = (const float*)d_in[0];
    const int*   ei    = (const int*)d_in[1];
    const int*   ntype = (const int*)d_in[2];
    const float* eattr = (const float*)d_in[3];
    const int*   etype = (const int*)d_in[4];
    const int*   eli   = (const int*)d_in[5];
    const float* Wx1   = (const float*)d_in[6];
    const float* We1   = (const float*)d_in[7];
    const float* nt1   = (const float*)d_in[8];
    const float* et1   = (const float*)d_in[9];
    const float* as1   = (const float*)d_in[10];
    const float* ad1   = (const float*)d_in[11];
    const float* ae1   = (const float*)d_in[12];
    const float* res1  = (const float*)d_in[13];
    const float* Wx2   = (const float*)d_in[14];
    const float* We2   = (const float*)d_in[15];
    const float* nt2   = (const float*)d_in[16];
    const float* et2   = (const float*)d_in[17];
    const float* as2   = (const float*)d_in[18];
    const float* ad2   = (const float*)d_in[19];
    const float* ae2   = (const float*)d_in[20];
    const float* W1    = (const float*)d_in[21];
    const float* b1    = (const float*)d_in[22];
    const float* W2    = (const float*)d_in[23];
    const float* b2    = (const float*)d_in[24];

    float* pred = (float*)d_out;
    float* zout = pred + ELN;

    size_t smP2 = 128 * 80 * 2 + 64 * 64 * 2 + 128 * 72 * 4 + 512 * 4 + 64 * 4 + 64 * 4 + 128 * 4;
    size_t smD  = 64 * 144 * 2 + 128 * 64 * 2 + 64 * 72 * 4 + 64 * 4 + 64 * 4 + 64 * 4 + 64 * 4;
    static bool attr_done = false;
    if (!attr_done) {
        cudaFuncSetAttribute((const void*)k_proj2, cudaFuncAttributeMaxDynamicSharedMemorySize, (int)smP2);
        cudaFuncSetAttribute((const void*)k_dec, cudaFuncAttributeMaxDynamicSharedMemorySize, (int)smD);
        attr_done = true;
    }

    // CSR build
    k_count<<<(EE + 255) / 256, 256>>>(ei);
    k_scanfuse<<<1, 1024>>>(We1, ae1, et1, We2, ae2, et2);
    k_fill<<<(EE + 255) / 256, 256>>>(ei, etype);

    // layer 1 (k_proj1 = 4th launch -> comparable profiled slot)
    k_proj1<<<592, 256>>>(x, ntype, nt1, Wx1, as1, ad1);
    k_score<1><<<(EE + 255) / 256, 256>>>(ei, eattr, etype);
    k_agg1<<<1184, 256>>>(eattr, We1, et1, x, res1);

    // layer 2
    k_proj2<<<dim3((NN + 127) / 128, 4), 256, smP2>>>(ntype, nt2, Wx2, as2, ad2);
    k_score<2><<<(EE + 255) / 256, 256>>>(ei, eattr, etype);
    k_agg2<<<1184, 256>>>(eattr, We2, et2, zout);

    // decoder
    k_dec<<<592, 256, smD>>>(eli, W1, b1, W2, b2, pred);
}

// round 16
// speedup vs baseline: 1.4512x; 1.0322x over previous
#include <cuda_runtime.h>
#include <cuda_fp16.h>
#include <mma.h>
#include <cstdint>

using namespace nvcuda;

#define NN 100000
#define EE 600000
#define ELN 200000

// ---------------- device scratch ----------------
__device__ __half g_hh[(size_t)NN * 64];    // layer1 node projections (fp16, col-pair layout)
__device__ __half g_h2h[(size_t)NN * 256];  // layer2 node projections (fp16)
__device__ float  g_z1[(size_t)NN * 64];    // layer1 output
__device__ __half g_zh[(size_t)NN * 64];    // fp16 shadow of final z (decoder gathers)
__device__ float  g_sc[(size_t)EE * 4];     // CSR-ordered EXP'd scores
__device__ float  g_ss[NN * 4];
__device__ float  g_sd[NN * 4];
__device__ int    g_cnt[NN];
__device__ int    g_rowptr[NN + 1];
__device__ int    g_cur[NN];
__device__ int    g_pos[EE];
__device__ int4   g_mt[EE];                 // CSR slot -> (src, etype, orig, 0)
__device__ float  g_wae1[64], g_tae1[88];
__device__ float  g_wae2[64], g_tae2[88];

// ---------------- CSR build ----------------
__global__ void k_count(const int* __restrict__ ei) {
    int e = blockIdx.x * blockDim.x + threadIdx.x;
    if (e < EE) atomicAdd(&g_cnt[ei[EE + e]], 1);
}

__global__ void k_scanfuse(const float* __restrict__ We1, const float* __restrict__ ae1,
                           const float* __restrict__ et1,
                           const float* __restrict__ We2, const float* __restrict__ ae2,
                           const float* __restrict__ et2) {
    __shared__ int sp[1024];
    int tid = threadIdx.x;
    if (tid < 64) {
        int k = tid >> 2, h = tid & 3;
        float s = 0.f;
        for (int d = 0; d < 16; d++) s += We1[k * 64 + h * 16 + d] * ae1[h * 16 + d];
        g_wae1[k * 4 + h] = s;
        float s2 = 0.f;
        for (int d = 0; d < 64; d++) s2 += We2[k * 256 + h * 64 + d] * ae2[h * 64 + d];
        g_wae2[k * 4 + h] = s2;
    }
    if (tid < 88) {
        int t = tid >> 2, h = tid & 3;
        float s = 0.f;
        for (int d = 0; d < 16; d++) s += et1[t * 64 + h * 16 + d] * ae1[h * 16 + d];
        g_tae1[t * 4 + h] = s;
        float s2 = 0.f;
        for (int d = 0; d < 64; d++) s2 += et2[t * 256 + h * 64 + d] * ae2[h * 64 + d];
        g_tae2[t * 4 + h] = s2;
    }
    const int chunk = (NN + 1023) >> 10;
    int st = tid * chunk;
    int en = st + chunk; if (en > NN) en = NN;
    int s = 0;
    for (int i = st; i < en; i++) s += g_cnt[i];
    sp[tid] = s;
    __syncthreads();
    for (int o = 1; o < 1024; o <<= 1) {
        int v = (tid >= o) ? sp[tid - o] : 0;
        __syncthreads();
        sp[tid] += v;
        __syncthreads();
    }
    int b = sp[tid] - s;
    for (int i = st; i < en; i++) {
        g_rowptr[i] = b; g_cur[i] = b; b += g_cnt[i];
        g_cnt[i] = 0;   // re-zero for next replay
    }
    if (tid == 1023) g_rowptr[NN] = sp[1023];
}

__global__ void k_fill(const int* __restrict__ ei, const int* __restrict__ etype) {
    int e = blockIdx.x * blockDim.x + threadIdx.x;
    if (e < EE) {
        int d = ei[EE + e];
        int p = atomicAdd(&g_cur[d], 1);
        g_pos[e] = p;
        g_mt[p] = make_int4(ei[e], etype[e], e, 0);
    }
}

// ---------------- layer1 node projection: persistent, Wx in registers, fp16 out ----------------
__global__ void __launch_bounds__(256) k_proj1(const float* __restrict__ x, const int* __restrict__ ntype,
                                               const float* __restrict__ nt, const float* __restrict__ Wx,
                                               const float* __restrict__ a_s, const float* __restrict__ a_d) {
    __shared__ float sNt[8 * 16];
    int tid = threadIdx.x, L = tid & 31, w = tid >> 5;
    for (int i = tid; i < 128; i += 256) sNt[i] = nt[i];

    float W0[16], W1r[16];
#pragma unroll
    for (int k = 0; k < 16; k++) {
        W0[k]  = __ldg(&Wx[k * 64 + 2 * L]);
        W1r[k] = __ldg(&Wx[k * 64 + 2 * L + 1]);
    }
    float as0 = __ldg(&a_s[2 * L]), as1 = __ldg(&a_s[2 * L + 1]);
    float ad0 = __ldg(&a_d[2 * L]), ad1 = __ldg(&a_d[2 * L + 1]);
    __syncthreads();

    const int H = L >> 3;
    int nwarps = gridDim.x * 8;
    for (int n = blockIdx.x * 8 + w; n < NN; n += nwarps) {
        int t = __ldg(&ntype[n]);
        float xv = 0.f;
        if (L < 16) xv = __ldg(&x[(size_t)n * 16 + L]) + sNt[t * 16 + L];
        float acc0 = 0.f, acc1 = 0.f;
#pragma unroll
        for (int k = 0; k < 16; k++) {
            float xk = __shfl_sync(0xffffffffu, xv, k);
            acc0 = fmaf(xk, W0[k], acc0);
            acc1 = fmaf(xk, W1r[k], acc1);
        }
        *(__half2*)&g_hh[(size_t)n * 64 + 2 * L] = __floats2half2_rn(acc0, acc1);

        float pa = acc0 * as0 + acc1 * as1;
        float qa = acc0 * ad0 + acc1 * ad1;
#pragma unroll
        for (int o = 4; o >= 1; o >>= 1) {
            pa += __shfl_xor_sync(0xffffffffu, pa, o);
            qa += __shfl_xor_sync(0xffffffffu, qa, o);
        }
        if ((L & 7) == 0) {
            g_ss[n * 4 + H] = pa;
            g_sd[n * 4 + H] = qa;
        }
    }
}

// ---------------- edge scores -> exp(leaky(score)), scattered to CSR slots ----------------
template <int LAYER>
__global__ void k_score(const int* __restrict__ ei, const float* __restrict__ eattr,
                        const int* __restrict__ etype) {
    __shared__ float sW[64];
    __shared__ float sT[88];
    const float* wae = (LAYER == 1) ? g_wae1 : g_wae2;
    const float* tae = (LAYER == 1) ? g_tae1 : g_tae2;
    if (threadIdx.x < 64) sW[threadIdx.x] = wae[threadIdx.x];
    if (threadIdx.x < 88) sT[threadIdx.x] = tae[threadIdx.x];
    __syncthreads();

    int e = blockIdx.x * blockDim.x + threadIdx.x;
    if (e >= EE) return;
    int s = ei[e], d = ei[EE + e], t = etype[e];
    float sc[4];
#pragma unroll
    for (int h = 0; h < 4; h++)
        sc[h] = g_ss[s * 4 + h] + g_sd[d * 4 + h] + sT[t * 4 + h];

    const float4* ea = (const float4*)(eattr + (size_t)e * 16);
#pragma unroll
    for (int q = 0; q < 4; q++) {
        float4 a = __ldg(ea + q);
#pragma unroll
        for (int h = 0; h < 4; h++) {
            sc[h] = fmaf(a.x, sW[(4 * q + 0) * 4 + h],
                    fmaf(a.y, sW[(4 * q + 1) * 4 + h],
                    fmaf(a.z, sW[(4 * q + 2) * 4 + h],
                    fmaf(a.w, sW[(4 * q + 3) * 4 + h], sc[h]))));
        }
    }
#pragma unroll
    for (int h = 0; h < 4; h++) {
        float v = (sc[h] > 0.f) ? sc[h] : 0.2f * sc[h];
        sc[h] = __expf(v);
    }
    int p = __ldg(&g_pos[e]);
    *(float4*)&g_sc[(size_t)p * 4] = make_float4(sc[0], sc[1], sc[2], sc[3]);
}

// ---------------- layer1 aggregation: persistent warps, sum-only softmax, fp16 h gathers ----------------
__global__ void __launch_bounds__(256) k_agg1(const float* __restrict__ eattr,
                                              const float* __restrict__ We, const float* __restrict__ et,
                                              const float* __restrict__ x, const float* __restrict__ res) {
    __shared__ float sEt[22 * 64];
    __shared__ float sWe[16 * 64];
    __shared__ float sRes[16 * 64];
    __shared__ float sWs[8 * 64];
    __shared__ float4 sAl[8][32];
    __shared__ int sS[8][32], sTt[8][32], sE[8][32];
    int tid = threadIdx.x, L = tid & 31, w = tid >> 5;
    for (int i = tid; i < 22 * 64; i += 256) sEt[i] = et[i];
    for (int i = tid; i < 16 * 64; i += 256) { sWe[i] = We[i]; sRes[i] = res[i]; }
    __syncthreads();

    const int H = L >> 3, hb = L >> 4;
    for (int n = blockIdx.x * 8 + w; n < NN; n += gridDim.x * 8) {
        int r0 = __ldg(&g_rowptr[n]), r1 = __ldg(&g_rowptr[n + 1]);

        // denominator: plain sum of exp'd scores (contiguous)
        float dd[4] = {0.f, 0.f, 0.f, 0.f};
        for (int i = r0 + L; i < r1; i += 32) {
            float4 s = *(const float4*)&g_sc[(size_t)i * 4];
            dd[0] += s.x; dd[1] += s.y; dd[2] += s.z; dd[3] += s.w;
        }
#pragma unroll
        for (int o = 16; o >= 1; o >>= 1) {
#pragma unroll
            for (int h = 0; h < 4; h++) dd[h] += __shfl_xor_sync(0xffffffffu, dd[h], o);
        }
        float inv[4];
#pragma unroll
        for (int h = 0; h < 4; h++) inv[h] = 1.f / (dd[h] + 1e-16f);

        float ax = 0.f, ay = 0.f;
        float w0 = 0.f, w1 = 0.f;
        for (int base = r0; base < r1; base += 32) {
            int nv = min(32, r1 - base);
            if (L < nv) {
                float4 s = *(const float4*)&g_sc[(size_t)(base + L) * 4];
                int4 mt = g_mt[base + L];
                sAl[w][L] = make_float4(s.x * inv[0], s.y * inv[1], s.z * inv[2], s.w * inv[3]);
                sS[w][L] = mt.x; sTt[w][L] = mt.y; sE[w][L] = mt.z;
            }
            __syncwarp();
            int sj = sS[w][0], tj = sTt[w][0], ej = sE[w][0];
            __half2 hr = *(const __half2*)&g_hh[(size_t)sj * 64 + 2 * L];
            float ea = __ldg(&eattr[(size_t)ej * 16 + (L & 15)]);
            for (int j = 0; j < nv; j++) {
                float4 al = sAl[w][j];
                float2 h2 = __half22float2(hr);
                float2 ev = *(const float2*)&sEt[tj * 64 + 2 * L];
                float ah = (H == 0) ? al.x : ((H == 1) ? al.y : ((H == 2) ? al.z : al.w));
                ax = fmaf(ah, h2.x + ev.x, ax);
                ay = fmaf(ah, h2.y + ev.y, ay);
                float aw0 = hb ? al.y : al.x, aw1 = hb ? al.w : al.z;
                w0 = fmaf(aw0, ea, w0);
                w1 = fmaf(aw1, ea, w1);
                if (j + 1 < nv) {
                    sj = sS[w][j + 1]; tj = sTt[w][j + 1]; ej = sE[w][j + 1];
                    hr = *(const __half2*)&g_hh[(size_t)sj * 64 + 2 * L];
                    ea = __ldg(&eattr[(size_t)ej * 16 + (L & 15)]);
                }
            }
            __syncwarp();
        }
        sWs[w * 64 + L] = w0;
        sWs[w * 64 + 32 + L] = w1;
        __syncwarp();
#pragma unroll
        for (int k = 0; k < 16; k++) {
            float wk = sWs[w * 64 + H * 16 + k];
            float2 we = *(const float2*)&sWe[k * 64 + 2 * L];
            ax = fmaf(wk, we.x, ax);
            ay = fmaf(wk, we.y, ay);
        }
        const float4* xp = (const float4*)(x + (size_t)n * 16);
        float4 xa = __ldg(xp), xb = __ldg(xp + 1), xc = __ldg(xp + 2), xd = __ldg(xp + 3);
        float xv[16] = {xa.x, xa.y, xa.z, xa.w, xb.x, xb.y, xb.z, xb.w,
                        xc.x, xc.y, xc.z, xc.w, xd.x, xd.y, xd.z, xd.w};
#pragma unroll
        for (int k = 0; k < 16; k++) {
            float2 rv = *(const float2*)&sRes[k * 64 + 2 * L];
            ax = fmaf(xv[k], rv.x, ax);
            ay = fmaf(xv[k], rv.y, ay);
        }
        *(float2*)&g_z1[(size_t)n * 64 + 2 * L] = make_float2(fmaxf(ax, 0.f), fmaxf(ay, 0.f));
        __syncwarp();
    }
}

// ---------------- layer2 projection: wmma fp16 GEMM + fused ss/sd, h stored fp16 ----------------
__global__ void __launch_bounds__(256) k_proj2(const int* __restrict__ ntype, const float* __restrict__ nt,
                                               const float* __restrict__ Wx,
                                               const float* __restrict__ a_s, const float* __restrict__ a_d) {
    extern __shared__ char smraw[];
    __half* sA = (__half*)smraw;          // 128 x 80
    __half* sB = sA + 128 * 80;           // 64 x 64
    float* sC  = (float*)(sB + 64 * 64);  // 128 x 72
    float* sNt = sC + 128 * 72;           // 512
    float* sAs = sNt + 512;               // 64
    float* sAd = sAs + 64;                // 64
    int*   sTy = (int*)(sAd + 64);        // 128

    int tid = threadIdx.x, L = tid & 31, w = tid >> 5;
    int by = blockIdx.y;
    int rbase = blockIdx.x * 128;

    for (int i = tid; i < 512; i += 256) sNt[i] = nt[i];
    if (tid < 64) { sAs[tid] = a_s[by * 64 + tid]; sAd[tid] = a_d[by * 64 + tid]; }
    if (tid < 128) { int r = rbase + tid; sTy[tid] = (r < NN) ? ntype[r] : 0; }
    for (int i = tid; i < 1024; i += 256) {
        int k = i >> 4, cg = i & 15;
        float4 v = *(const float4*)&Wx[(size_t)k * 256 + by * 64 + cg * 4];
        __half2 a = __floats2half2_rn(v.x, v.y);
        __half2 b = __floats2half2_rn(v.z, v.w);
        uint2 pk; pk.x = *(unsigned*)&a; pk.y = *(unsigned*)&b;
        *(uint2*)&sB[k * 64 + cg * 4] = pk;
    }
    __syncthreads();
    for (int i = tid; i < 2048; i += 256) {
        int r = i >> 4, sg = i & 15;
        int gr = rbase + r;
        float4 v = make_float4(0.f, 0.f, 0.f, 0.f);
        if (gr < NN) {
            v = *(const float4*)&g_z1[(size_t)gr * 64 + sg * 4];
            float4 nv = *(const float4*)&sNt[sTy[r] * 64 + sg * 4];
            v.x += nv.x; v.y += nv.y; v.z += nv.z; v.w += nv.w;
        }
        __half2 a = __floats2half2_rn(v.x, v.y);
        __half2 b = __floats2half2_rn(v.z, v.w);
        uint2 pk; pk.x = *(unsigned*)&a; pk.y = *(unsigned*)&b;
        *(uint2*)&sA[r * 80 + sg * 4] = pk;
    }
    __syncthreads();

    wmma::fragment<wmma::accumulator, 16, 16, 16, float> fc[4];
#pragma unroll
    for (int c = 0; c < 4; c++) wmma::fill_fragment(fc[c], 0.f);
    for (int k0 = 0; k0 < 64; k0 += 16) {
        wmma::fragment<wmma::matrix_a, 16, 16, 16, __half, wmma::row_major> fa;
        wmma::load_matrix_sync(fa, &sA[w * 16 * 80 + k0], 80);
#pragma unroll
        for (int c = 0; c < 4; c++) {
            wmma::fragment<wmma::matrix_b, 16, 16, 16, __half, wmma::row_major> fb;
            wmma::load_matrix_sync(fb, &sB[k0 * 64 + c * 16], 64);
            wmma::mma_sync(fc[c], fa, fb, fc[c]);
        }
    }
    __syncwarp();
#pragma unroll
    for (int c = 0; c < 4; c++)
        wmma::store_matrix_sync(&sC[w * 16 * 72 + c * 16], fc[c], 72, wmma::mem_row_major);
    __syncwarp();

    for (int r = 0; r < 16; r++) {
        int gr = rbase + w * 16 + r;
        if (gr >= NN) break;
        float h0 = sC[(w * 16 + r) * 72 + L];
        float h1 = sC[(w * 16 + r) * 72 + 32 + L];
        __half2 hp = __floats2half2_rn(h0, h1);
        g_h2h[(size_t)gr * 256 + by * 64 + L] = __low2half(hp);
        g_h2h[(size_t)gr * 256 + by * 64 + 32 + L] = __high2half(hp);
        float ps = h0 * sAs[L] + h1 * sAs[32 + L];
        float pd = h0 * sAd[L] + h1 * sAd[32 + L];
#pragma unroll
        for (int o = 16; o >= 1; o >>= 1) {
            ps += __shfl_xor_sync(0xffffffffu, ps, o);
            pd += __shfl_xor_sync(0xffffffffu, pd, o);
        }
        if (L == 0) { g_ss[gr * 4 + by] = ps; g_sd[gr * 4 + by] = pd; }
    }
}

// ---------------- layer2 aggregation: persistent warps, sum-only softmax, fp16 h gathers ----------------
__global__ void __launch_bounds__(256) k_agg2(const float* __restrict__ eattr,
                                              const float* __restrict__ We, const float* __restrict__ et,
                                              float* __restrict__ zout) {
    __shared__ float4 sEt[22 * 64];
    __shared__ float4 sWe[16 * 64];
    __shared__ float  sWs[8 * 64];
    __shared__ float4 sAl[8][32];
    __shared__ int sS[8][32], sTt[8][32], sE[8][32];
    int tid = threadIdx.x, L = tid & 31, w = tid >> 5;
    for (int i = tid; i < 22 * 64; i += 256) sEt[i] = *(const float4*)&et[(size_t)i * 4];
    for (int i = tid; i < 16 * 64; i += 256) sWe[i] = *(const float4*)&We[(size_t)i * 4];
    __syncthreads();

    const int hb = L >> 4;
    for (int n = blockIdx.x * 8 + w; n < NN; n += gridDim.x * 8) {
        int r0 = __ldg(&g_rowptr[n]), r1 = __ldg(&g_rowptr[n + 1]);

        float dd[4] = {0.f, 0.f, 0.f, 0.f};
        for (int i = r0 + L; i < r1; i += 32) {
            float4 s = *(const float4*)&g_sc[(size_t)i * 4];
            dd[0] += s.x; dd[1] += s.y; dd[2] += s.z; dd[3] += s.w;
        }
#pragma unroll
        for (int o = 16; o >= 1; o >>= 1) {
#pragma unroll
            for (int h = 0; h < 4; h++) dd[h] += __shfl_xor_sync(0xffffffffu, dd[h], o);
        }
        float inv[4];
#pragma unroll
        for (int h = 0; h < 4; h++) inv[h] = 1.f / (dd[h] + 1e-16f);

        float4 acc0 = make_float4(0.f, 0.f, 0.f, 0.f);
        float4 acc1 = make_float4(0.f, 0.f, 0.f, 0.f);
        float w0 = 0.f, w1 = 0.f;

        for (int base = r0; base < r1; base += 32) {
            int nv = min(32, r1 - base);
            if (L < nv) {
                float4 s = *(const float4*)&g_sc[(size_t)(base + L) * 4];
                int4 mt = g_mt[base + L];
                sAl[w][L] = make_float4(s.x * inv[0], s.y * inv[1], s.z * inv[2], s.w * inv[3]);
                sS[w][L] = mt.x; sTt[w][L] = mt.y; sE[w][L] = mt.z;
            }
            __syncwarp();
            int sj = sS[w][0], tj = sTt[w][0], ej = sE[w][0];
            uint2 raw0 = *(const uint2*)&g_h2h[(size_t)sj * 256 + 4 * L];
            uint2 raw1 = *(const uint2*)&g_h2h[(size_t)sj * 256 + 128 + 4 * L];
            float ea = __ldg(&eattr[(size_t)ej * 16 + (L & 15)]);
            for (int j = 0; j < nv; j++) {
                float4 al = sAl[w][j];
                float2 h0a = __half22float2(*(__half2*)&raw0.x);
                float2 h0b = __half22float2(*(__half2*)&raw0.y);
                float2 h1a = __half22float2(*(__half2*)&raw1.x);
                float2 h1b = __half22float2(*(__half2*)&raw1.y);
                float4 e0 = sEt[tj * 64 + L];
                float4 e1 = sEt[tj * 64 + 32 + L];
                float aA = hb ? al.y : al.x;
                float aB = hb ? al.w : al.z;
                acc0.x = fmaf(aA, h0a.x + e0.x, acc0.x);
                acc0.y = fmaf(aA, h0a.y + e0.y, acc0.y);
                acc0.z = fmaf(aA, h0b.x + e0.z, acc0.z);
                acc0.w = fmaf(aA, h0b.y + e0.w, acc0.w);
                acc1.x = fmaf(aB, h1a.x + e1.x, acc1.x);
                acc1.y = fmaf(aB, h1a.y + e1.y, acc1.y);
                acc1.z = fmaf(aB, h1b.x + e1.z, acc1.z);
                acc1.w = fmaf(aB, h1b.y + e1.w, acc1.w);
                w0 = fmaf(aA, ea, w0);
                w1 = fmaf(aB, ea, w1);
                if (j + 1 < nv) {
                    sj = sS[w][j + 1]; tj = sTt[w][j + 1]; ej = sE[w][j + 1];
                    raw0 = *(const uint2*)&g_h2h[(size_t)sj * 256 + 4 * L];
                    raw1 = *(const uint2*)&g_h2h[(size_t)sj * 256 + 128 + 4 * L];
                    ea = __ldg(&eattr[(size_t)ej * 16 + (L & 15)]);
                }
            }
            __syncwarp();
        }
        sWs[w * 64 + L] = w0;
        sWs[w * 64 + 32 + L] = w1;
        __syncwarp();

        const int H0i = hb, H1i = 2 + hb;
#pragma unroll
        for (int k = 0; k < 16; k++) {
            float k0 = sWs[w * 64 + H0i * 16 + k];
            float k1 = sWs[w * 64 + H1i * 16 + k];
            float4 we0 = sWe[k * 64 + L];
            float4 we1 = sWe[k * 64 + 32 + L];
            acc0.x = fmaf(k0, we0.x, acc0.x); acc0.y = fmaf(k0, we0.y, acc0.y);
            acc0.z = fmaf(k0, we0.z, acc0.z); acc0.w = fmaf(k0, we0.w, acc0.w);
            acc1.x = fmaf(k1, we1.x, acc1.x); acc1.y = fmaf(k1, we1.y, acc1.y);
            acc1.z = fmaf(k1, we1.z, acc1.z); acc1.w = fmaf(k1, we1.w, acc1.w);
        }
        float4 sm4;
        sm4.x = acc0.x + acc1.x; sm4.y = acc0.y + acc1.y;
        sm4.z = acc0.z + acc1.z; sm4.w = acc0.w + acc1.w;
        sm4.x += __shfl_xor_sync(0xffffffffu, sm4.x, 16);
        sm4.y += __shfl_xor_sync(0xffffffffu, sm4.y, 16);
        sm4.z += __shfl_xor_sync(0xffffffffu, sm4.z, 16);
        sm4.w += __shfl_xor_sync(0xffffffffu, sm4.w, 16);
        if (L < 16) {
            float4 z1v = *(const float4*)&g_z1[(size_t)n * 64 + 4 * L];
            float4 o;
            o.x = z1v.x + 0.25f * sm4.x;
            o.y = z1v.y + 0.25f * sm4.y;
            o.z = z1v.z + 0.25f * sm4.z;
            o.w = z1v.w + 0.25f * sm4.w;
            *(float4*)&zout[(size_t)n * 64 + 4 * L] = o;
            __half2 za = __floats2half2_rn(o.x, o.y);
            __half2 zb = __floats2half2_rn(o.z, o.w);
            uint2 pk; pk.x = *(unsigned*)&za; pk.y = *(unsigned*)&zb;
            *(uint2*)&g_zh[(size_t)n * 64 + 4 * L] = pk;
        }
        __syncwarp();
    }
}

// ---------------- decoder: persistent wmma fp16 GEMM, fp16 z gathers ----------------
__global__ void __launch_bounds__(256) k_dec(const int* __restrict__ eli,
                                             const float* __restrict__ W1, const float* __restrict__ b1,
                                             const float* __restrict__ W2, const float* __restrict__ b2,
                                             float* __restrict__ pred) {
    extern __shared__ char smraw[];
    __half* sA = (__half*)smraw;            // 64 x 144
    __half* sB = sA + 64 * 144;             // 128 x 64
    float* sC  = (float*)(sB + 128 * 64);   // 64 x 72
    int*   sR  = (int*)(sC + 64 * 72);      // 64
    int*   sCn = sR + 64;                   // 64
    float* sb1 = (float*)(sCn + 64);        // 64
    float* sw2 = sb1 + 64;                  // 64

    int tid = threadIdx.x, L = tid & 31, w = tid >> 5;
    if (tid < 64) { sb1[tid] = b1[tid]; sw2[tid] = W2[tid]; }
    for (int i = tid; i < 2048; i += 256) {
        float4 v = *(const float4*)&W1[(size_t)i * 4];
        __half2 a = __floats2half2_rn(v.x, v.y);
        __half2 b = __floats2half2_rn(v.z, v.w);
        uint2 pk; pk.x = *(unsigned*)&a; pk.y = *(unsigned*)&b;
        *(uint2*)&sB[i * 4] = pk;
    }

    float bb = __ldg(&b2[0]);
    const int rt = w >> 1;
    const int ch = w & 1;

    const int NT = ELN / 64;
    for (int tile = blockIdx.x; tile < NT; tile += gridDim.x) {
        int ebase = tile * 64;
        __syncthreads();
        if (tid < 64) sR[tid] = __ldg(&eli[ebase + tid]);
        else if (tid < 128) sCn[tid - 64] = __ldg(&eli[ELN + ebase + tid - 64]);
        __syncthreads();
        for (int i = tid; i < 1024; i += 256) {
            int e = i >> 4, sg = i & 15;
            int node = (sg < 8) ? sR[e] : sCn[e];
            uint4 v = *(const uint4*)&g_zh[(size_t)node * 64 + (sg & 7) * 8];
            *(uint4*)&sA[e * 144 + sg * 8] = v;
        }
        __syncthreads();

        wmma::fragment<wmma::accumulator, 16, 16, 16, float> fc[2];
        wmma::fill_fragment(fc[0], 0.f);
        wmma::fill_fragment(fc[1], 0.f);
        for (int k0 = 0; k0 < 128; k0 += 16) {
            wmma::fragment<wmma::matrix_a, 16, 16, 16, __half, wmma::row_major> fa;
            wmma::load_matrix_sync(fa, &sA[rt * 16 * 144 + k0], 144);
#pragma unroll
            for (int cc = 0; cc < 2; cc++) {
                wmma::fragment<wmma::matrix_b, 16, 16, 16, __half, wmma::row_major> fb;
                wmma::load_matrix_sync(fb, &sB[k0 * 64 + (ch * 2 + cc) * 16], 64);
                wmma::mma_sync(fc[cc], fa, fb, fc[cc]);
            }
        }
#pragma unroll
        for (int cc = 0; cc < 2; cc++)
            wmma::store_matrix_sync(&sC[rt * 16 * 72 + (ch * 2 + cc) * 16], fc[cc], 72, wmma::mem_row_major);
        __syncthreads();

        for (int r = 0; r < 8; r++) {
            int row = w * 8 + r;
            float hx = fmaxf(sC[row * 72 + L] + sb1[L], 0.f);
            float hy = fmaxf(sC[row * 72 + 32 + L] + sb1[32 + L], 0.f);
            float p = hx * sw2[L] + hy * sw2[32 + L];
#pragma unroll
            for (int o = 16; o >= 1; o >>= 1) p += __shfl_xor_sync(0xffffffffu, p, o);
            if (L == 0) pred[ebase + row] = p + bb;
        }
    }
}

// ---------------- launch ----------------
extern "C" void kernel_launch(void* const* d_in, const int* in_sizes, int n_in,
                              void* d_out, int out_size) {
    const float* x     = (const float*)d_in[0];
    const int*   ei    = (const int*)d_in[1];
    const int*   ntype = (const int*)d_in[2];
    const float* eattr = (const float*)d_in[3];
    const int*   etype = (const int*)d_in[4];
    const int*   eli   = (const int*)d_in[5];
    const float* Wx1   = (const float*)d_in[6];
    const float* We1   = (const float*)d_in[7];
    const float* nt1   = (const float*)d_in[8];
    const float* et1   = (const float*)d_in[9];
    const float* as1   = (const float*)d_in[10];
    const float* ad1   = (const float*)d_in[11];
    const float* ae1   = (const float*)d_in[12];
    const float* res1  = (const float*)d_in[13];
    const float* Wx2   = (const float*)d_in[14];
    const float* We2   = (const float*)d_in[15];
    const float* nt2   = (const float*)d_in[16];
    const float* et2   = (const float*)d_in[17];
    const float* as2   = (const float*)d_in[18];
    const float* ad2   = (const float*)d_in[19];
    const float* ae2   = (const float*)d_in[20];
    const float* W1    = (const float*)d_in[21];
    const float* b1    = (const float*)d_in[22];
    const float* W2    = (const float*)d_in[23];
    const float* b2    = (const float*)d_in[24];

    float* pred = (float*)d_out;
    float* zout = pred + ELN;

    size_t smP2 = 128 * 80 * 2 + 64 * 64 * 2 + 128 * 72 * 4 + 512 * 4 + 64 * 4 + 64 * 4 + 128 * 4;
    size_t smD  = 64 * 144 * 2 + 128 * 64 * 2 + 64 * 72 * 4 + 64 * 4 + 64 * 4 + 64 * 4 + 64 * 4;
    static cudaStream_t sSide = nullptr;
    static cudaEvent_t evFork = nullptr, evJoin = nullptr;
    if (!sSide) {
        cudaFuncSetAttribute((const void*)k_proj2, cudaFuncAttributeMaxDynamicSharedMemorySize, (int)smP2);
        cudaFuncSetAttribute((const void*)k_dec, cudaFuncAttributeMaxDynamicSharedMemorySize, (int)smD);
        cudaStreamCreate(&sSide);
        cudaEventCreateWithFlags(&evFork, cudaEventDisableTiming);
        cudaEventCreateWithFlags(&evJoin, cudaEventDisableTiming);
    }

    // fork: proj1 on side stream, CSR build on main stream (independent)
    cudaEventRecord(evFork, 0);
    cudaStreamWaitEvent(sSide, evFork, 0);
    k_proj1<<<592, 256, 0, sSide>>>(x, ntype, nt1, Wx1, as1, ad1);
    cudaEventRecord(evJoin, sSide);

    k_count<<<(EE + 255) / 256, 256>>>(ei);
    k_scanfuse<<<1, 1024>>>(We1, ae1, et1, We2, ae2, et2);
    k_fill<<<(EE + 255) / 256, 256>>>(ei, etype);

    cudaStreamWaitEvent(0, evJoin, 0);  // join before score1

    // layer 1
    k_score<1><<<(EE + 255) / 256, 256>>>(ei, eattr, etype);
    k_agg1<<<1184, 256>>>(eattr, We1, et1, x, res1);

    // layer 2
    k_proj2<<<dim3((NN + 127) / 128, 4), 256, smP2>>>(ntype, nt2, Wx2, as2, ad2);
    k_score<2><<<(EE + 255) / 256, 256>>>(ei, eattr, etype);
    k_agg2<<<1184, 256>>>(eattr, We2, et2, zout);

    // decoder
    k_dec<<<592, 256, smD>>>(eli, W1, b1, W2, b2, pred);
}

// round 17
// speedup vs baseline: 1.4547x; 1.0024x over previous
#include <cuda_runtime.h>
#include <cuda_fp16.h>
#include <mma.h>
#include <cstdint>

using namespace nvcuda;

#define NN 100000
#define EE 600000
#define ELN 200000

// ---------------- device scratch ----------------
__device__ __half g_hh[(size_t)NN * 64];    // layer1 node projections (fp16, col-pair layout)
__device__ __half g_h2h[(size_t)NN * 256];  // layer2 node projections (fp16)
__device__ float  g_z1[(size_t)NN * 64];    // layer1 output
__device__ __half g_zh[(size_t)NN * 64];    // fp16 shadow of final z (decoder gathers)
__device__ float  g_sc[(size_t)EE * 4];     // CSR-ordered EXP'd scores
__device__ __half g_eah[(size_t)EE * 16];   // CSR-ordered fp16 eattr copy
__device__ float  g_ss[NN * 4];
__device__ float  g_sd[NN * 4];
__device__ int    g_cnt[NN];
__device__ int    g_rowptr[NN + 1];
__device__ int    g_cur[NN];
__device__ int    g_pos[EE];
__device__ int4   g_mt[EE];                 // CSR slot -> (src, etype, orig, 0)
__device__ float  g_wae1[64], g_tae1[88];
__device__ float  g_wae2[64], g_tae2[88];

// ---------------- CSR build ----------------
__global__ void k_count(const int* __restrict__ ei) {
    int e = blockIdx.x * blockDim.x + threadIdx.x;
    if (e < EE) atomicAdd(&g_cnt[ei[EE + e]], 1);
}

__global__ void k_scanfuse(const float* __restrict__ We1, const float* __restrict__ ae1,
                           const float* __restrict__ et1,
                           const float* __restrict__ We2, const float* __restrict__ ae2,
                           const float* __restrict__ et2) {
    __shared__ int sp[1024];
    int tid = threadIdx.x;
    if (tid < 64) {
        int k = tid >> 2, h = tid & 3;
        float s = 0.f;
        for (int d = 0; d < 16; d++) s += We1[k * 64 + h * 16 + d] * ae1[h * 16 + d];
        g_wae1[k * 4 + h] = s;
        float s2 = 0.f;
        for (int d = 0; d < 64; d++) s2 += We2[k * 256 + h * 64 + d] * ae2[h * 64 + d];
        g_wae2[k * 4 + h] = s2;
    }
    if (tid < 88) {
        int t = tid >> 2, h = tid & 3;
        float s = 0.f;
        for (int d = 0; d < 16; d++) s += et1[t * 64 + h * 16 + d] * ae1[h * 16 + d];
        g_tae1[t * 4 + h] = s;
        float s2 = 0.f;
        for (int d = 0; d < 64; d++) s2 += et2[t * 256 + h * 64 + d] * ae2[h * 64 + d];
        g_tae2[t * 4 + h] = s2;
    }
    const int chunk = (NN + 1023) >> 10;
    int st = tid * chunk;
    int en = st + chunk; if (en > NN) en = NN;
    int s = 0;
    for (int i = st; i < en; i++) s += g_cnt[i];
    sp[tid] = s;
    __syncthreads();
    for (int o = 1; o < 1024; o <<= 1) {
        int v = (tid >= o) ? sp[tid - o] : 0;
        __syncthreads();
        sp[tid] += v;
        __syncthreads();
    }
    int b = sp[tid] - s;
    for (int i = st; i < en; i++) {
        g_rowptr[i] = b; g_cur[i] = b; b += g_cnt[i];
        g_cnt[i] = 0;   // re-zero for next replay
    }
    if (tid == 1023) g_rowptr[NN] = sp[1023];
}

__global__ void k_fill(const int* __restrict__ ei, const int* __restrict__ etype) {
    int e = blockIdx.x * blockDim.x + threadIdx.x;
    if (e < EE) {
        int d = ei[EE + e];
        int p = atomicAdd(&g_cur[d], 1);
        g_pos[e] = p;
        g_mt[p] = make_int4(ei[e], etype[e], e, 0);
    }
}

// ---------------- layer1 node projection: persistent, Wx in registers, fp16 out ----------------
__global__ void __launch_bounds__(256) k_proj1(const float* __restrict__ x, const int* __restrict__ ntype,
                                               const float* __restrict__ nt, const float* __restrict__ Wx,
                                               const float* __restrict__ a_s, const float* __restrict__ a_d) {
    __shared__ float sNt[8 * 16];
    int tid = threadIdx.x, L = tid & 31, w = tid >> 5;
    for (int i = tid; i < 128; i += 256) sNt[i] = nt[i];

    float W0[16], W1r[16];
#pragma unroll
    for (int k = 0; k < 16; k++) {
        W0[k]  = __ldg(&Wx[k * 64 + 2 * L]);
        W1r[k] = __ldg(&Wx[k * 64 + 2 * L + 1]);
    }
    float as0 = __ldg(&a_s[2 * L]), as1 = __ldg(&a_s[2 * L + 1]);
    float ad0 = __ldg(&a_d[2 * L]), ad1 = __ldg(&a_d[2 * L + 1]);
    __syncthreads();

    const int H = L >> 3;
    int nwarps = gridDim.x * 8;
    for (int n = blockIdx.x * 8 + w; n < NN; n += nwarps) {
        int t = __ldg(&ntype[n]);
        float xv = 0.f;
        if (L < 16) xv = __ldg(&x[(size_t)n * 16 + L]) + sNt[t * 16 + L];
        float acc0 = 0.f, acc1 = 0.f;
#pragma unroll
        for (int k = 0; k < 16; k++) {
            float xk = __shfl_sync(0xffffffffu, xv, k);
            acc0 = fmaf(xk, W0[k], acc0);
            acc1 = fmaf(xk, W1r[k], acc1);
        }
        *(__half2*)&g_hh[(size_t)n * 64 + 2 * L] = __floats2half2_rn(acc0, acc1);

        float pa = acc0 * as0 + acc1 * as1;
        float qa = acc0 * ad0 + acc1 * ad1;
#pragma unroll
        for (int o = 4; o >= 1; o >>= 1) {
            pa += __shfl_xor_sync(0xffffffffu, pa, o);
            qa += __shfl_xor_sync(0xffffffffu, qa, o);
        }
        if ((L & 7) == 0) {
            g_ss[n * 4 + H] = pa;
            g_sd[n * 4 + H] = qa;
        }
    }
}

// ---------------- edge scores -> exp(leaky(score)) + fp16 eattr copy, CSR slots ----------------
template <int LAYER>
__global__ void k_score(const int* __restrict__ ei, const float* __restrict__ eattr,
                        const int* __restrict__ etype) {
    __shared__ float sW[64];
    __shared__ float sT[88];
    const float* wae = (LAYER == 1) ? g_wae1 : g_wae2;
    const float* tae = (LAYER == 1) ? g_tae1 : g_tae2;
    if (threadIdx.x < 64) sW[threadIdx.x] = wae[threadIdx.x];
    if (threadIdx.x < 88) sT[threadIdx.x] = tae[threadIdx.x];
    __syncthreads();

    int e = blockIdx.x * blockDim.x + threadIdx.x;
    if (e >= EE) return;
    int s = ei[e], d = ei[EE + e], t = etype[e];
    float sc[4];
#pragma unroll
    for (int h = 0; h < 4; h++)
        sc[h] = g_ss[s * 4 + h] + g_sd[d * 4 + h] + sT[t * 4 + h];

    float4 av[4];
    const float4* ea = (const float4*)(eattr + (size_t)e * 16);
#pragma unroll
    for (int q = 0; q < 4; q++) {
        float4 a = __ldg(ea + q);
        av[q] = a;
#pragma unroll
        for (int h = 0; h < 4; h++) {
            sc[h] = fmaf(a.x, sW[(4 * q + 0) * 4 + h],
                    fmaf(a.y, sW[(4 * q + 1) * 4 + h],
                    fmaf(a.z, sW[(4 * q + 2) * 4 + h],
                    fmaf(a.w, sW[(4 * q + 3) * 4 + h], sc[h]))));
        }
    }
#pragma unroll
    for (int h = 0; h < 4; h++) {
        float v = (sc[h] > 0.f) ? sc[h] : 0.2f * sc[h];
        sc[h] = __expf(v);
    }
    int p = __ldg(&g_pos[e]);
    *(float4*)&g_sc[(size_t)p * 4] = make_float4(sc[0], sc[1], sc[2], sc[3]);
    if (LAYER == 1) {
        // write fp16 eattr copy at CSR slot (layer-invariant; write once)
        uint4 u0, u1;
        __half2 h01 = __floats2half2_rn(av[0].x, av[0].y), h23 = __floats2half2_rn(av[0].z, av[0].w);
        __half2 h45 = __floats2half2_rn(av[1].x, av[1].y), h67 = __floats2half2_rn(av[1].z, av[1].w);
        u0.x = *(unsigned*)&h01; u0.y = *(unsigned*)&h23; u0.z = *(unsigned*)&h45; u0.w = *(unsigned*)&h67;
        __half2 h89 = __floats2half2_rn(av[2].x, av[2].y), hab = __floats2half2_rn(av[2].z, av[2].w);
        __half2 hcd = __floats2half2_rn(av[3].x, av[3].y), hef = __floats2half2_rn(av[3].z, av[3].w);
        u1.x = *(unsigned*)&h89; u1.y = *(unsigned*)&hab; u1.z = *(unsigned*)&hcd; u1.w = *(unsigned*)&hef;
        *(uint4*)&g_eah[(size_t)p * 16] = u0;
        *(uint4*)&g_eah[(size_t)p * 16 + 8] = u1;
    }
}

// ---------------- layer1 aggregation: sum-only softmax, fp16 gathers, 2-deep prefetch ----------------
__global__ void __launch_bounds__(256) k_agg1(const float* __restrict__ We, const float* __restrict__ et,
                                              const float* __restrict__ x, const float* __restrict__ res) {
    __shared__ float sEt[22 * 64];
    __shared__ float sWe[16 * 64];
    __shared__ float sRes[16 * 64];
    __shared__ float sWs[8 * 64];
    __shared__ float4 sAl[8][32];
    __shared__ int sS[8][32], sTt[8][32];
    int tid = threadIdx.x, L = tid & 31, w = tid >> 5;
    for (int i = tid; i < 22 * 64; i += 256) sEt[i] = et[i];
    for (int i = tid; i < 16 * 64; i += 256) { sWe[i] = We[i]; sRes[i] = res[i]; }
    __syncthreads();

    const int H = L >> 3, hb = L >> 4;
    const int eL = L & 15;
    for (int n = blockIdx.x * 8 + w; n < NN; n += gridDim.x * 8) {
        int r0 = __ldg(&g_rowptr[n]), r1 = __ldg(&g_rowptr[n + 1]);

        float dd[4] = {0.f, 0.f, 0.f, 0.f};
        for (int i = r0 + L; i < r1; i += 32) {
            float4 s = *(const float4*)&g_sc[(size_t)i * 4];
            dd[0] += s.x; dd[1] += s.y; dd[2] += s.z; dd[3] += s.w;
        }
#pragma unroll
        for (int o = 16; o >= 1; o >>= 1) {
#pragma unroll
            for (int h = 0; h < 4; h++) dd[h] += __shfl_xor_sync(0xffffffffu, dd[h], o);
        }
        float inv[4];
#pragma unroll
        for (int h = 0; h < 4; h++) inv[h] = 1.f / (dd[h] + 1e-16f);

        float ax = 0.f, ay = 0.f;
        float w0 = 0.f, w1 = 0.f;
        for (int base = r0; base < r1; base += 32) {
            int nv = min(32, r1 - base);
            if (L < nv) {
                float4 s = *(const float4*)&g_sc[(size_t)(base + L) * 4];
                int4 mt = g_mt[base + L];
                sAl[w][L] = make_float4(s.x * inv[0], s.y * inv[1], s.z * inv[2], s.w * inv[3]);
                sS[w][L] = mt.x; sTt[w][L] = mt.y;
            }
            __syncwarp();
            // 2-deep prefetch: A = edge j, B = edge j+1
            __half2 hA = *(const __half2*)&g_hh[(size_t)sS[w][0] * 64 + 2 * L];
            __half eaA = g_eah[(size_t)(base + 0) * 16 + eL];
            __half2 hB = hA; __half eaB = eaA;
            if (nv > 1) {
                hB = *(const __half2*)&g_hh[(size_t)sS[w][1] * 64 + 2 * L];
                eaB = g_eah[(size_t)(base + 1) * 16 + eL];
            }
            for (int j = 0; j < nv; j++) {
                float4 al = sAl[w][j];
                int tj = sTt[w][j];
                float2 h2 = __half22float2(hA);
                float eaf = __half2float(eaA);
                float2 ev = *(const float2*)&sEt[tj * 64 + 2 * L];
                float ah = (H == 0) ? al.x : ((H == 1) ? al.y : ((H == 2) ? al.z : al.w));
                ax = fmaf(ah, h2.x + ev.x, ax);
                ay = fmaf(ah, h2.y + ev.y, ay);
                float aw0 = hb ? al.y : al.x, aw1 = hb ? al.w : al.z;
                w0 = fmaf(aw0, eaf, w0);
                w1 = fmaf(aw1, eaf, w1);
                hA = hB; eaA = eaB;
                if (j + 2 < nv) {
                    hB = *(const __half2*)&g_hh[(size_t)sS[w][j + 2] * 64 + 2 * L];
                    eaB = g_eah[(size_t)(base + j + 2) * 16 + eL];
                }
            }
            __syncwarp();
        }
        sWs[w * 64 + L] = w0;
        sWs[w * 64 + 32 + L] = w1;
        __syncwarp();
#pragma unroll
        for (int k = 0; k < 16; k++) {
            float wk = sWs[w * 64 + H * 16 + k];
            float2 we = *(const float2*)&sWe[k * 64 + 2 * L];
            ax = fmaf(wk, we.x, ax);
            ay = fmaf(wk, we.y, ay);
        }
        const float4* xp = (const float4*)(x + (size_t)n * 16);
        float4 xa = __ldg(xp), xb = __ldg(xp + 1), xc = __ldg(xp + 2), xd = __ldg(xp + 3);
        float xv[16] = {xa.x, xa.y, xa.z, xa.w, xb.x, xb.y, xb.z, xb.w,
                        xc.x, xc.y, xc.z, xc.w, xd.x, xd.y, xd.z, xd.w};
#pragma unroll
        for (int k = 0; k < 16; k++) {
            float2 rv = *(const float2*)&sRes[k * 64 + 2 * L];
            ax = fmaf(xv[k], rv.x, ax);
            ay = fmaf(xv[k], rv.y, ay);
        }
        *(float2*)&g_z1[(size_t)n * 64 + 2 * L] = make_float2(fmaxf(ax, 0.f), fmaxf(ay, 0.f));
        __syncwarp();
    }
}

// ---------------- layer2 projection: wmma fp16 GEMM + fused ss/sd, h stored fp16 ----------------
__global__ void __launch_bounds__(256) k_proj2(const int* __restrict__ ntype, const float* __restrict__ nt,
                                               const float* __restrict__ Wx,
                                               const float* __restrict__ a_s, const float* __restrict__ a_d) {
    extern __shared__ char smraw[];
    __half* sA = (__half*)smraw;          // 128 x 80
    __half* sB = sA + 128 * 80;           // 64 x 64
    float* sC  = (float*)(sB + 64 * 64);  // 128 x 72
    float* sNt = sC + 128 * 72;           // 512
    float* sAs = sNt + 512;               // 64
    float* sAd = sAs + 64;                // 64
    int*   sTy = (int*)(sAd + 64);        // 128

    int tid = threadIdx.x, L = tid & 31, w = tid >> 5;
    int by = blockIdx.y;
    int rbase = blockIdx.x * 128;

    for (int i = tid; i < 512; i += 256) sNt[i] = nt[i];
    if (tid < 64) { sAs[tid] = a_s[by * 64 + tid]; sAd[tid] = a_d[by * 64 + tid]; }
    if (tid < 128) { int r = rbase + tid; sTy[tid] = (r < NN) ? ntype[r] : 0; }
    for (int i = tid; i < 1024; i += 256) {
        int k = i >> 4, cg = i & 15;
        float4 v = *(const float4*)&Wx[(size_t)k * 256 + by * 64 + cg * 4];
        __half2 a = __floats2half2_rn(v.x, v.y);
        __half2 b = __floats2half2_rn(v.z, v.w);
        uint2 pk; pk.x = *(unsigned*)&a; pk.y = *(unsigned*)&b;
        *(uint2*)&sB[k * 64 + cg * 4] = pk;
    }
    __syncthreads();
    for (int i = tid; i < 2048; i += 256) {
        int r = i >> 4, sg = i & 15;
        int gr = rbase + r;
        float4 v = make_float4(0.f, 0.f, 0.f, 0.f);
        if (gr < NN) {
            v = *(const float4*)&g_z1[(size_t)gr * 64 + sg * 4];
            float4 nv = *(const float4*)&sNt[sTy[r] * 64 + sg * 4];
            v.x += nv.x; v.y += nv.y; v.z += nv.z; v.w += nv.w;
        }
        __half2 a = __floats2half2_rn(v.x, v.y);
        __half2 b = __floats2half2_rn(v.z, v.w);
        uint2 pk; pk.x = *(unsigned*)&a; pk.y = *(unsigned*)&b;
        *(uint2*)&sA[r * 80 + sg * 4] = pk;
    }
    __syncthreads();

    wmma::fragment<wmma::accumulator, 16, 16, 16, float> fc[4];
#pragma unroll
    for (int c = 0; c < 4; c++) wmma::fill_fragment(fc[c], 0.f);
    for (int k0 = 0; k0 < 64; k0 += 16) {
        wmma::fragment<wmma::matrix_a, 16, 16, 16, __half, wmma::row_major> fa;
        wmma::load_matrix_sync(fa, &sA[w * 16 * 80 + k0], 80);
#pragma unroll
        for (int c = 0; c < 4; c++) {
            wmma::fragment<wmma::matrix_b, 16, 16, 16, __half, wmma::row_major> fb;
            wmma::load_matrix_sync(fb, &sB[k0 * 64 + c * 16], 64);
            wmma::mma_sync(fc[c], fa, fb, fc[c]);
        }
    }
    __syncwarp();
#pragma unroll
    for (int c = 0; c < 4; c++)
        wmma::store_matrix_sync(&sC[w * 16 * 72 + c * 16], fc[c], 72, wmma::mem_row_major);
    __syncwarp();

    for (int r = 0; r < 16; r++) {
        int gr = rbase + w * 16 + r;
        if (gr >= NN) break;
        float h0 = sC[(w * 16 + r) * 72 + L];
        float h1 = sC[(w * 16 + r) * 72 + 32 + L];
        __half2 hp = __floats2half2_rn(h0, h1);
        g_h2h[(size_t)gr * 256 + by * 64 + L] = __low2half(hp);
        g_h2h[(size_t)gr * 256 + by * 64 + 32 + L] = __high2half(hp);
        float ps = h0 * sAs[L] + h1 * sAs[32 + L];
        float pd = h0 * sAd[L] + h1 * sAd[32 + L];
#pragma unroll
        for (int o = 16; o >= 1; o >>= 1) {
            ps += __shfl_xor_sync(0xffffffffu, ps, o);
            pd += __shfl_xor_sync(0xffffffffu, pd, o);
        }
        if (L == 0) { g_ss[gr * 4 + by] = ps; g_sd[gr * 4 + by] = pd; }
    }
}

// ---------------- layer2 aggregation: sum-only softmax, fp16 gathers, 2-deep prefetch ----------------
__global__ void __launch_bounds__(256) k_agg2(const float* __restrict__ We, const float* __restrict__ et,
                                              float* __restrict__ zout) {
    __shared__ float4 sEt[22 * 64];
    __shared__ float4 sWe[16 * 64];
    __shared__ float  sWs[8 * 64];
    __shared__ float4 sAl[8][32];
    __shared__ int sS[8][32], sTt[8][32];
    int tid = threadIdx.x, L = tid & 31, w = tid >> 5;
    for (int i = tid; i < 22 * 64; i += 256) sEt[i] = *(const float4*)&et[(size_t)i * 4];
    for (int i = tid; i < 16 * 64; i += 256) sWe[i] = *(const float4*)&We[(size_t)i * 4];
    __syncthreads();

    const int hb = L >> 4;
    const int eL = L & 15;
    for (int n = blockIdx.x * 8 + w; n < NN; n += gridDim.x * 8) {
        int r0 = __ldg(&g_rowptr[n]), r1 = __ldg(&g_rowptr[n + 1]);

        float dd[4] = {0.f, 0.f, 0.f, 0.f};
        for (int i = r0 + L; i < r1; i += 32) {
            float4 s = *(const float4*)&g_sc[(size_t)i * 4];
            dd[0] += s.x; dd[1] += s.y; dd[2] += s.z; dd[3] += s.w;
        }
#pragma unroll
        for (int o = 16; o >= 1; o >>= 1) {
#pragma unroll
            for (int h = 0; h < 4; h++) dd[h] += __shfl_xor_sync(0xffffffffu, dd[h], o);
        }
        float inv[4];
#pragma unroll
        for (int h = 0; h < 4; h++) inv[h] = 1.f / (dd[h] + 1e-16f);

        float4 acc0 = make_float4(0.f, 0.f, 0.f, 0.f);
        float4 acc1 = make_float4(0.f, 0.f, 0.f, 0.f);
        float w0 = 0.f, w1 = 0.f;

        for (int base = r0; base < r1; base += 32) {
            int nv = min(32, r1 - base);
            if (L < nv) {
                float4 s = *(const float4*)&g_sc[(size_t)(base + L) * 4];
                int4 mt = g_mt[base + L];
                sAl[w][L] = make_float4(s.x * inv[0], s.y * inv[1], s.z * inv[2], s.w * inv[3]);
                sS[w][L] = mt.x; sTt[w][L] = mt.y;
            }
            __syncwarp();
            // 2-deep prefetch
            uint2 A0, A1, B0, B1;
            __half eaA, eaB;
            {
                int sj = sS[w][0];
                A0 = *(const uint2*)&g_h2h[(size_t)sj * 256 + 4 * L];
                A1 = *(const uint2*)&g_h2h[(size_t)sj * 256 + 128 + 4 * L];
                eaA = g_eah[(size_t)(base + 0) * 16 + eL];
            }
            B0 = A0; B1 = A1; eaB = eaA;
            if (nv > 1) {
                int sj = sS[w][1];
                B0 = *(const uint2*)&g_h2h[(size_t)sj * 256 + 4 * L];
                B1 = *(const uint2*)&g_h2h[(size_t)sj * 256 + 128 + 4 * L];
                eaB = g_eah[(size_t)(base + 1) * 16 + eL];
            }
            for (int j = 0; j < nv; j++) {
                float4 al = sAl[w][j];
                int tj = sTt[w][j];
                float2 h0a = __half22float2(*(__half2*)&A0.x);
                float2 h0b = __half22float2(*(__half2*)&A0.y);
                float2 h1a = __half22float2(*(__half2*)&A1.x);
                float2 h1b = __half22float2(*(__half2*)&A1.y);
                float eaf = __half2float(eaA);
                float4 e0 = sEt[tj * 64 + L];
                float4 e1 = sEt[tj * 64 + 32 + L];
                float aA = hb ? al.y : al.x;
                float aB = hb ? al.w : al.z;
                acc0.x = fmaf(aA, h0a.x + e0.x, acc0.x);
                acc0.y = fmaf(aA, h0a.y + e0.y, acc0.y);
                acc0.z = fmaf(aA, h0b.x + e0.z, acc0.z);
                acc0.w = fmaf(aA, h0b.y + e0.w, acc0.w);
                acc1.x = fmaf(aB, h1a.x + e1.x, acc1.x);
                acc1.y = fmaf(aB, h1a.y + e1.y, acc1.y);
                acc1.z = fmaf(aB, h1b.x + e1.z, acc1.z);
                acc1.w = fmaf(aB, h1b.y + e1.w, acc1.w);
                w0 = fmaf(aA, eaf, w0);
                w1 = fmaf(aB, eaf, w1);
                A0 = B0; A1 = B1; eaA = eaB;
                if (j + 2 < nv) {
                    int sj = sS[w][j + 2];
                    B0 = *(const uint2*)&g_h2h[(size_t)sj * 256 + 4 * L];
                    B1 = *(const uint2*)&g_h2h[(size_t)sj * 256 + 128 + 4 * L];
                    eaB = g_eah[(size_t)(base + j + 2) * 16 + eL];
                }
            }
            __syncwarp();
        }
        sWs[w * 64 + L] = w0;
        sWs[w * 64 + 32 + L] = w1;
        __syncwarp();

        const int H0i = hb, H1i = 2 + hb;
#pragma unroll
        for (int k = 0; k < 16; k++) {
            float k0 = sWs[w * 64 + H0i * 16 + k];
            float k1 = sWs[w * 64 + H1i * 16 + k];
            float4 we0 = sWe[k * 64 + L];
            float4 we1 = sWe[k * 64 + 32 + L];
            acc0.x = fmaf(k0, we0.x, acc0.x); acc0.y = fmaf(k0, we0.y, acc0.y);
            acc0.z = fmaf(k0, we0.z, acc0.z); acc0.w = fmaf(k0, we0.w, acc0.w);
            acc1.x = fmaf(k1, we1.x, acc1.x); acc1.y = fmaf(k1, we1.y, acc1.y);
            acc1.z = fmaf(k1, we1.z, acc1.z); acc1.w = fmaf(k1, we1.w, acc1.w);
        }
        float4 sm4;
        sm4.x = acc0.x + acc1.x; sm4.y = acc0.y + acc1.y;
        sm4.z = acc0.z + acc1.z; sm4.w = acc0.w + acc1.w;
        sm4.x += __shfl_xor_sync(0xffffffffu, sm4.x, 16);
        sm4.y += __shfl_xor_sync(0xffffffffu, sm4.y, 16);
        sm4.z += __shfl_xor_sync(0xffffffffu, sm4.z, 16);
        sm4.w += __shfl_xor_sync(0xffffffffu, sm4.w, 16);
        if (L < 16) {
            float4 z1v = *(const float4*)&g_z1[(size_t)n * 64 + 4 * L];
            float4 o;
            o.x = z1v.x + 0.25f * sm4.x;
            o.y = z1v.y + 0.25f * sm4.y;
            o.z = z1v.z + 0.25f * sm4.z;
            o.w = z1v.w + 0.25f * sm4.w;
            *(float4*)&zout[(size_t)n * 64 + 4 * L] = o;
            __half2 za = __floats2half2_rn(o.x, o.y);
            __half2 zb = __floats2half2_rn(o.z, o.w);
            uint2 pk; pk.x = *(unsigned*)&za; pk.y = *(unsigned*)&zb;
            *(uint2*)&g_zh[(size_t)n * 64 + 4 * L] = pk;
        }
        __syncwarp();
    }
}

// ---------------- decoder: persistent wmma fp16 GEMM, fp16 z gathers ----------------
__global__ void __launch_bounds__(256) k_dec(const int* __restrict__ eli,
                                             const float* __restrict__ W1, const float* __restrict__ b1,
                                             const float* __restrict__ W2, const float* __restrict__ b2,
                                             float* __restrict__ pred) {
    extern __shared__ char smraw[];
    __half* sA = (__half*)smraw;            // 64 x 144
    __half* sB = sA + 64 * 144;             // 128 x 64
    float* sC  = (float*)(sB + 128 * 64);   // 64 x 72
    int*   sR  = (int*)(sC + 64 * 72);      // 64
    int*   sCn = sR + 64;                   // 64
    float* sb1 = (float*)(sCn + 64);        // 64
    float* sw2 = sb1 + 64;                  // 64

    int tid = threadIdx.x, L = tid & 31, w = tid >> 5;
    if (tid < 64) { sb1[tid] = b1[tid]; sw2[tid] = W2[tid]; }
    for (int i = tid; i < 2048; i += 256) {
        float4 v = *(const float4*)&W1[(size_t)i * 4];
        __half2 a = __floats2half2_rn(v.x, v.y);
        __half2 b = __floats2half2_rn(v.z, v.w);
        uint2 pk; pk.x = *(unsigned*)&a; pk.y = *(unsigned*)&b;
        *(uint2*)&sB[i * 4] = pk;
    }

    float bb = __ldg(&b2[0]);
    const int rt = w >> 1;
    const int ch = w & 1;

    const int NT = ELN / 64;
    for (int tile = blockIdx.x; tile < NT; tile += gridDim.x) {
        int ebase = tile * 64;
        __syncthreads();
        if (tid < 64) sR[tid] = __ldg(&eli[ebase + tid]);
        else if (tid < 128) sCn[tid - 64] = __ldg(&eli[ELN + ebase + tid - 64]);
        __syncthreads();
        for (int i = tid; i < 1024; i += 256) {
            int e = i >> 4, sg = i & 15;
            int node = (sg < 8) ? sR[e] : sCn[e];
            uint4 v = *(const uint4*)&g_zh[(size_t)node * 64 + (sg & 7) * 8];
            *(uint4*)&sA[e * 144 + sg * 8] = v;
        }
        __syncthreads();

        wmma::fragment<wmma::accumulator, 16, 16, 16, float> fc[2];
        wmma::fill_fragment(fc[0], 0.f);
        wmma::fill_fragment(fc[1], 0.f);
        for (int k0 = 0; k0 < 128; k0 += 16) {
            wmma::fragment<wmma::matrix_a, 16, 16, 16, __half, wmma::row_major> fa;
            wmma::load_matrix_sync(fa, &sA[rt * 16 * 144 + k0], 144);
#pragma unroll
            for (int cc = 0; cc < 2; cc++) {
                wmma::fragment<wmma::matrix_b, 16, 16, 16, __half, wmma::row_major> fb;
                wmma::load_matrix_sync(fb, &sB[k0 * 64 + (ch * 2 + cc) * 16], 64);
                wmma::mma_sync(fc[cc], fa, fb, fc[cc]);
            }
        }
#pragma unroll
        for (int cc = 0; cc < 2; cc++)
            wmma::store_matrix_sync(&sC[rt * 16 * 72 + (ch * 2 + cc) * 16], fc[cc], 72, wmma::mem_row_major);
        __syncthreads();

        for (int r = 0; r < 8; r++) {
            int row = w * 8 + r;
            float hx = fmaxf(sC[row * 72 + L] + sb1[L], 0.f);
            float hy = fmaxf(sC[row * 72 + 32 + L] + sb1[32 + L], 0.f);
            float p = hx * sw2[L] + hy * sw2[32 + L];
#pragma unroll
            for (int o = 16; o >= 1; o >>= 1) p += __shfl_xor_sync(0xffffffffu, p, o);
            if (L == 0) pred[ebase + row] = p + bb;
        }
    }
}

// ---------------- launch ----------------
extern "C" void kernel_launch(void* const* d_in, const int* in_sizes, int n_in,
                              void* d_out, int out_size) {
    const float* x     = (const float*)d_in[0];
    const int*   ei    = (const int*)d_in[1];
    const int*   ntype = (const int*)d_in[2];
    const float* eattr = (const float*)d_in[3];
    const int*   etype = (const int*)d_in[4];
    const int*   eli   = (const int*)d_in[5];
    const float* Wx1   = (const float*)d_in[6];
    const float* We1   = (const float*)d_in[7];
    const float* nt1   = (const float*)d_in[8];
    const float* et1   = (const float*)d_in[9];
    const float* as1   = (const float*)d_in[10];
    const float* ad1   = (const float*)d_in[11];
    const float* ae1   = (const float*)d_in[12];
    const float* res1  = (const float*)d_in[13];
    const float* Wx2   = (const float*)d_in[14];
    const float* We2   = (const float*)d_in[15];
    const float* nt2   = (const float*)d_in[16];
    const float* et2   = (const float*)d_in[17];
    const float* as2   = (const float*)d_in[18];
    const float* ad2   = (const float*)d_in[19];
    const float* ae2   = (const float*)d_in[20];
    const float* W1    = (const float*)d_in[21];
    const float* b1    = (const float*)d_in[22];
    const float* W2    = (const float*)d_in[23];
    const float* b2    = (const float*)d_in[24];

    float* pred = (float*)d_out;
    float* zout = pred + ELN;

    size_t smP2 = 128 * 80 * 2 + 64 * 64 * 2 + 128 * 72 * 4 + 512 * 4 + 64 * 4 + 64 * 4 + 128 * 4;
    size_t smD  = 64 * 144 * 2 + 128 * 64 * 2 + 64 * 72 * 4 + 64 * 4 + 64 * 4 + 64 * 4 + 64 * 4;
    static cudaStream_t sSide = nullptr;
    static cudaEvent_t evFork = nullptr, evJoin = nullptr;
    if (!sSide) {
        cudaFuncSetAttribute((const void*)k_proj2, cudaFuncAttributeMaxDynamicSharedMemorySize, (int)smP2);
        cudaFuncSetAttribute((const void*)k_dec, cudaFuncAttributeMaxDynamicSharedMemorySize, (int)smD);
        cudaStreamCreate(&sSide);
        cudaEventCreateWithFlags(&evFork, cudaEventDisableTiming);
        cudaEventCreateWithFlags(&evJoin, cudaEventDisableTiming);
    }

    // fork: proj1 on side stream, CSR build on main stream (independent)
    cudaEventRecord(evFork, 0);
    cudaStreamWaitEvent(sSide, evFork, 0);
    k_proj1<<<592, 256, 0, sSide>>>(x, ntype, nt1, Wx1, as1, ad1);
    cudaEventRecord(evJoin, sSide);

    k_count<<<(EE + 255) / 256, 256>>>(ei);
    k_scanfuse<<<1, 1024>>>(We1, ae1, et1, We2, ae2, et2);
    k_fill<<<(EE + 255) / 256, 256>>>(ei, etype);

    cudaStreamWaitEvent(0, evJoin, 0);  // join before score1

    // layer 1
    k_score<1><<<(EE + 255) / 256, 256>>>(ei, eattr, etype);
    k_agg1<<<1184, 256>>>(We1, et1, x, res1);

    // layer 2
    k_proj2<<<dim3((NN + 127) / 128, 4), 256, smP2>>>(ntype, nt2, Wx2, as2, ad2);
    k_score<2><<<(EE + 255) / 256, 256>>>(ei, eattr, etype);
    k_agg2<<<1184, 256>>>(We2, et2, zout);

    // decoder
    k_dec<<<592, 256, smD>>>(eli, W1, b1, W2, b2, pred);
}